// round 13
// baseline (speedup 1.0000x reference)
#include <cuda_runtime.h>
#include <cuda_bf16.h>
#include <cstdint>

#define NN 50000
#define NE 800000
#define EPS_LN 1e-5f

// ---------------- scratch (no allocations allowed) ----------------
__device__ __align__(128) float g_agg[NN * 64];
__device__ __align__(128) float g_y[(size_t)NN * 128];   // edge-layer node partials
__device__ __align__(128) float g_y2[(size_t)NN * 64];   // node-layer x partial
__device__ __align__(128) __nv_bfloat16 g_xhi[NN * 64], g_xlo[NN * 64];
__device__ __align__(128) __nv_bfloat16 g_ehi[(size_t)NE * 64], g_elo[(size_t)NE * 64];
// CSR (built once per launch; edge_index is constant)
__device__ int g_cnt[NN];
__device__ int g_cur[NN];
__device__ int g_off[NN + 1];
__device__ int g_perm[NE];

// ---------------- helpers ----------------
__device__ __forceinline__ uint32_t smem_u32(const void* p) {
    uint32_t a;
    asm("{ .reg .u64 t; cvta.to.shared.u64 t, %1; cvt.u32.u64 %0, t; }" : "=r"(a) : "l"(p));
    return a;
}
__device__ __forceinline__ void split2(float f0, float f1, uint32_t& hi, uint32_t& lo) {
    uint32_t h;
    asm("cvt.rn.bf16x2.f32 %0, %1, %2;" : "=r"(h) : "f"(f1), "f"(f0));
    float h0 = __uint_as_float(h << 16);
    float h1 = __uint_as_float(h & 0xFFFF0000u);
    asm("cvt.rn.bf16x2.f32 %0, %1, %2;" : "=r"(lo) : "f"(f1 - h1), "f"(f0 - h0));
    hi = h;
}
__device__ __forceinline__ float2 join2(uint32_t hh, uint32_t ll) {
    float2 v;
    v.x = __uint_as_float(hh << 16) + __uint_as_float(ll << 16);
    v.y = __uint_as_float(hh & 0xFFFF0000u) + __uint_as_float(ll & 0xFFFF0000u);
    return v;
}
__device__ __forceinline__ void ldm4(uint32_t r[4], uint32_t a) {
    asm volatile("ldmatrix.sync.aligned.m8n8.x4.shared.b16 {%0,%1,%2,%3}, [%4];"
                 : "=r"(r[0]), "=r"(r[1]), "=r"(r[2]), "=r"(r[3]) : "r"(a));
}
__device__ __forceinline__ void mma16816(float d[4], const uint32_t a[4],
                                         uint32_t b0, uint32_t b1) {
    asm volatile("mma.sync.aligned.m16n8k16.row.col.f32.bf16.bf16.f32 "
                 "{%0,%1,%2,%3},{%4,%5,%6,%7},{%8,%9},{%0,%1,%2,%3};"
                 : "+f"(d[0]), "+f"(d[1]), "+f"(d[2]), "+f"(d[3])
                 : "r"(a[0]), "r"(a[1]), "r"(a[2]), "r"(a[3]), "r"(b0), "r"(b1));
}
__device__ __forceinline__ void cpasync16(uint32_t dst, const void* src) {
    asm volatile("cp.async.ca.shared.global [%0], [%1], 16;" :: "r"(dst), "l"(src));
}
#define CP_COMMIT() asm volatile("cp.async.commit_group;" ::: "memory")
#define CP_WAIT0()  asm volatile("cp.async.wait_group 0;" ::: "memory")
#define CP_WAIT1()  asm volatile("cp.async.wait_group 1;" ::: "memory")

// ---- A from smem, TWO m16 tiles share B; caller initializes d ----
template <int KT>
__device__ __forceinline__ void layer_smemA2(float (&d)[2][8][4],
        const uint32_t (&aHi)[2], const uint32_t (&aLo)[2],
        uint32_t bHi, uint32_t bLo, int bstep) {
#pragma unroll
    for (int kt = 0; kt < KT; kt++) {
        uint32_t ah[2][4], al[2][4];
        ldm4(ah[0], aHi[0] + kt * 32); ldm4(al[0], aLo[0] + kt * 32);
        ldm4(ah[1], aHi[1] + kt * 32); ldm4(al[1], aLo[1] + kt * 32);
        uint32_t bh[4][4], bl[4][4];
#pragma unroll
        for (int np = 0; np < 4; np++) {
            ldm4(bh[np], bHi + np * bstep + kt * 32);
            ldm4(bl[np], bLo + np * bstep + kt * 32);
        }
#pragma unroll
        for (int np = 0; np < 4; np++)
#pragma unroll
            for (int t = 0; t < 2; t++) {
                mma16816(d[t][2 * np],     ah[t], bh[np][0], bh[np][1]);
                mma16816(d[t][2 * np + 1], ah[t], bh[np][2], bh[np][3]);
            }
#pragma unroll
        for (int np = 0; np < 4; np++)
#pragma unroll
            for (int t = 0; t < 2; t++) {
                mma16816(d[t][2 * np],     ah[t], bl[np][0], bl[np][1]);
                mma16816(d[t][2 * np + 1], ah[t], bl[np][2], bl[np][3]);
            }
#pragma unroll
        for (int np = 0; np < 4; np++)
#pragma unroll
            for (int t = 0; t < 2; t++) {
                mma16816(d[t][2 * np],     al[t], bh[np][0], bh[np][1]);
                mma16816(d[t][2 * np + 1], al[t], bh[np][2], bh[np][3]);
            }
    }
}

// ---- A in registers (K=64), two tiles share B ----
__device__ __forceinline__ void layer_regA2(float (&d)[2][8][4],
        const uint32_t (&aH)[2][4][4], const uint32_t (&aL)[2][4][4],
        uint32_t bHi, uint32_t bLo, int bstep) {
#pragma unroll
    for (int t = 0; t < 2; t++)
#pragma unroll
        for (int nt = 0; nt < 8; nt++)
            d[t][nt][0] = d[t][nt][1] = d[t][nt][2] = d[t][nt][3] = 0.f;
#pragma unroll
    for (int kt = 0; kt < 4; kt++) {
        uint32_t bh[4][4], bl[4][4];
#pragma unroll
        for (int np = 0; np < 4; np++) {
            ldm4(bh[np], bHi + np * bstep + kt * 32);
            ldm4(bl[np], bLo + np * bstep + kt * 32);
        }
#pragma unroll
        for (int np = 0; np < 4; np++)
#pragma unroll
            for (int t = 0; t < 2; t++) {
                mma16816(d[t][2 * np],     aH[t][kt], bh[np][0], bh[np][1]);
                mma16816(d[t][2 * np + 1], aH[t][kt], bh[np][2], bh[np][3]);
            }
#pragma unroll
        for (int np = 0; np < 4; np++)
#pragma unroll
            for (int t = 0; t < 2; t++) {
                mma16816(d[t][2 * np],     aH[t][kt], bl[np][0], bl[np][1]);
                mma16816(d[t][2 * np + 1], aH[t][kt], bl[np][2], bl[np][3]);
            }
#pragma unroll
        for (int np = 0; np < 4; np++)
#pragma unroll
            for (int t = 0; t < 2; t++) {
                mma16816(d[t][2 * np],     aL[t][kt], bh[np][0], bh[np][1]);
                mma16816(d[t][2 * np + 1], aL[t][kt], bh[np][2], bh[np][3]);
            }
    }
}

// accumulator fragments -> next-layer A fragments, in registers
__device__ __forceinline__ void inter_reg2(const float (&d)[2][8][4], const float* bias, int c,
                                           uint32_t (&aH)[2][4][4], uint32_t (&aL)[2][4][4]) {
#pragma unroll
    for (int t = 0; t < 2; t++)
#pragma unroll
        for (int kt = 0; kt < 4; kt++) {
            float2 b0 = *(const float2*)(bias + 16 * kt + 2 * c);
            split2(fmaxf(d[t][2 * kt][0] + b0.x, 0.f), fmaxf(d[t][2 * kt][1] + b0.y, 0.f),
                   aH[t][kt][0], aL[t][kt][0]);
            split2(fmaxf(d[t][2 * kt][2] + b0.x, 0.f), fmaxf(d[t][2 * kt][3] + b0.y, 0.f),
                   aH[t][kt][1], aL[t][kt][1]);
            float2 b1 = *(const float2*)(bias + 16 * kt + 8 + 2 * c);
            split2(fmaxf(d[t][2 * kt + 1][0] + b1.x, 0.f), fmaxf(d[t][2 * kt + 1][1] + b1.y, 0.f),
                   aH[t][kt][2], aL[t][kt][2]);
            split2(fmaxf(d[t][2 * kt + 1][2] + b1.x, 0.f), fmaxf(d[t][2 * kt + 1][3] + b1.y, 0.f),
                   aH[t][kt][3], aL[t][kt][3]);
        }
}

// stage W[k][n] (row-major) as B[n][k] hi/lo with row stride bstr bytes
__device__ __forceinline__ void stage_w(char* dsth, char* dstl, const float* W,
                                        int K, int bstr, int tid, int nthr) {
    for (int idx = tid; idx < K * 64; idx += nthr) {
        int k = idx >> 6, n = idx & 63;
        float f = W[idx];
        __nv_bfloat16 h = __float2bfloat16_rn(f);
        __nv_bfloat16 l = __float2bfloat16_rn(f - __bfloat162float(h));
        int off = n * bstr + k * 2;
        *(__nv_bfloat16*)(dsth + off) = h;
        *(__nv_bfloat16*)(dstl + off) = l;
    }
}

// ================= CSR BUILD (once per launch) =================
__global__ void build_zero() {
    for (int i = blockIdx.x * blockDim.x + threadIdx.x; i < NN; i += gridDim.x * blockDim.x) {
        g_cnt[i] = 0; g_cur[i] = 0;
    }
}
__global__ void build_hist(const int* __restrict__ dst) {
    for (int e = blockIdx.x * blockDim.x + threadIdx.x; e < NE; e += gridDim.x * blockDim.x)
        atomicAdd(&g_cnt[dst[e]], 1);
}
__global__ void __launch_bounds__(1024) build_scan() {
    __shared__ int sums[1024];
    const int t = threadIdx.x;
    const int C = (NN + 1023) / 1024;
    const int lo = t * C, hi = min((t + 1) * C, NN);
    int s = 0;
    for (int i = lo; i < hi; i++) s += g_cnt[i];
    sums[t] = s;
    __syncthreads();
    for (int o = 1; o < 1024; o <<= 1) {
        int v = (t >= o) ? sums[t - o] : 0;
        __syncthreads();
        sums[t] += v;
        __syncthreads();
    }
    int base = (t == 0) ? 0 : sums[t - 1];
    for (int i = lo; i < hi; i++) {
        g_off[i] = base;
        base += g_cnt[i];
    }
    if (t == 1023) g_off[NN] = base;
}
__global__ void build_fill(const int* __restrict__ dst) {
    for (int e = blockIdx.x * blockDim.x + threadIdx.x; e < NE; e += gridDim.x * blockDim.x) {
        int dn = dst[e];
        int pos = atomicAdd(&g_cur[dn], 1);
        g_perm[g_off[dn] + pos] = e;
    }
}

// ================= AGGREGATION (CSR gather; no atomics) =================
// one warp per node; 4 edge-slots x 8 col-octets per warp
__global__ void __launch_bounds__(256) agg_kernel() {
    const int gw = (blockIdx.x * 256 + threadIdx.x) >> 5;
    const int lane = threadIdx.x & 31;
    const int slot = lane >> 3, oct = lane & 7;
    const int nwarps = gridDim.x * 8;
    for (int n = gw; n < NN; n += nwarps) {
        float acc[8];
#pragma unroll
        for (int i = 0; i < 8; i++) acc[i] = 0.f;
        const int beg = g_off[n], end = g_off[n + 1];
        for (int p = beg + slot; p < end; p += 4) {
            const int e = g_perm[p];
            const uint4 h4 = ((const uint4*)(g_ehi + (size_t)e * 64))[oct];
            const uint4 l4 = ((const uint4*)(g_elo + (size_t)e * 64))[oct];
            float2 v;
            v = join2(h4.x, l4.x); acc[0] += v.x; acc[1] += v.y;
            v = join2(h4.y, l4.y); acc[2] += v.x; acc[3] += v.y;
            v = join2(h4.z, l4.z); acc[4] += v.x; acc[5] += v.y;
            v = join2(h4.w, l4.w); acc[6] += v.x; acc[7] += v.y;
        }
#pragma unroll
        for (int i = 0; i < 8; i++) {
            acc[i] += __shfl_xor_sync(0xffffffffu, acc[i], 8);
            acc[i] += __shfl_xor_sync(0xffffffffu, acc[i], 16);
        }
        if (slot == 0) {
            float4* o = (float4*)(g_agg + (size_t)n * 64 + oct * 8);
            o[0] = make_float4(acc[0], acc[1], acc[2], acc[3]);
            o[1] = make_float4(acc[4], acc[5], acc[6], acc[7]);
        }
    }
}

// ================= NODE-PARTIAL PRECOMPUTE (MMA) =================
#define PRE_SMEM 129024

__global__ void __launch_bounds__(256, 1) node_pre_kernel(
    const float* __restrict__ eW0, const float* __restrict__ nW0)
{
    extern __shared__ char sm[];
    const int tid = threadIdx.x, wid = tid >> 5, lane = tid & 31;
    const uint32_t smb = smem_u32(sm);

    for (int idx = tid; idx < 192 * 64; idx += 256) {
        int j = idx >> 6, k = idx & 63;
        float f;
        if (j < 64)       f = eW0[k * 64 + j];
        else if (j < 128) f = eW0[(k + 64) * 64 + (j - 64)];
        else              f = nW0[k * 64 + (j - 128)];
        __nv_bfloat16 h = __float2bfloat16_rn(f);
        __nv_bfloat16 l = __float2bfloat16_rn(f - __bfloat162float(h));
        int off = j * 144 + k * 2;
        *(__nv_bfloat16*)(sm + 73728 + off) = h;
        *(__nv_bfloat16*)(sm + 101376 + off) = l;
    }
    __syncthreads();

    char* aHiP = sm + wid * 4608;
    char* aLoP = sm + 36864 + wid * 4608;
    const uint32_t aHiB = smb + wid * 4608, aLoB = smb + 36864 + wid * 4608;

    const int tq = lane >> 3;
    const int rA = (lane & 7) + ((tq & 1) << 3);
    const int kA = (tq >> 1) << 3;
    const uint32_t aHi[2] = { aHiB + rA * 144 + kA * 2, aHiB + (16 + rA) * 144 + kA * 2 };
    const uint32_t aLo[2] = { aLoB + rA * 144 + kA * 2, aLoB + (16 + rA) * 144 + kA * 2 };
    const int ofsB144 = ((tq >> 1) * 8 + (lane & 7)) * 144 + (tq & 1) * 16;
    const uint32_t bh = smb + 73728 + ofsB144, bl = smb + 101376 + ofsB144;

    const int g = lane >> 2, c = lane & 3;

    const int NWT = (NN + 31) / 32;
    for (int wt = blockIdx.x * 8 + wid; wt < NWT; wt += gridDim.x * 8) {
        {
            const int n = wt * 32 + lane;
            const int nc = (n < NN) ? n : (NN - 1);
            const uint4* s0 = (const uint4*)(g_xhi + (size_t)nc * 64);
            const uint4* s1 = (const uint4*)(g_xlo + (size_t)nc * 64);
            uint4* dh = (uint4*)(aHiP + lane * 144);
            uint4* dl = (uint4*)(aLoP + lane * 144);
#pragma unroll
            for (int j = 0; j < 8; j++) { dh[j] = s0[j]; dl[j] = s1[j]; }
        }
        __syncwarp();

#pragma unroll
        for (int half = 0; half < 3; half++) {
            float d[2][8][4];
#pragma unroll
            for (int t = 0; t < 2; t++)
#pragma unroll
                for (int nt = 0; nt < 8; nt++)
                    d[t][nt][0] = d[t][nt][1] = d[t][nt][2] = d[t][nt][3] = 0.f;
            layer_smemA2<4>(d, aHi, aLo, bh + half * 4 * 2304, bl + half * 4 * 2304, 2304);
#pragma unroll
            for (int t = 0; t < 2; t++) {
                const int n0 = wt * 32 + 16 * t + g, n1 = n0 + 8;
                const bool v0 = n0 < NN, v1 = n1 < NN;
#pragma unroll
                for (int nt = 0; nt < 8; nt++) {
                    const int col = nt * 8 + 2 * c;
                    if (half < 2) {
                        if (v0) *(float2*)(g_y + (size_t)n0 * 128 + half * 64 + col)
                                    = make_float2(d[t][nt][0], d[t][nt][1]);
                        if (v1) *(float2*)(g_y + (size_t)n1 * 128 + half * 64 + col)
                                    = make_float2(d[t][nt][2], d[t][nt][3]);
                    } else {
                        if (v0) *(float2*)(g_y2 + (size_t)n0 * 64 + col)
                                    = make_float2(d[t][nt][0], d[t][nt][1]);
                        if (v1) *(float2*)(g_y2 + (size_t)n1 * 64 + col)
                                    = make_float2(d[t][nt][2], d[t][nt][3]);
                    }
                }
            }
        }
        __syncwarp();
    }
}

// ================= EDGE KERNEL (no atomics) =================
#define E_SMEM 204032

__global__ void __launch_bounds__(256, 1) edge_kernel(
    float* eout,
    const int* __restrict__ src, const int* __restrict__ dst,
    const float* __restrict__ W0, const float* __restrict__ b0,
    const float* __restrict__ W1, const float* __restrict__ b1,
    const float* __restrict__ W2, const float* __restrict__ b2,
    const float* __restrict__ gam, const float* __restrict__ bet, int fin)
{
    extern __shared__ char sm[];
    const int tid = threadIdx.x, wid = tid >> 5, lane = tid & 31;
    const uint32_t smb = smem_u32(sm);

    stage_w(sm + 147456, sm + 156672, W0 + 128 * 64, 64, 144, tid, 256);
    stage_w(sm + 165888, sm + 175104, W1, 64, 144, tid, 256);
    stage_w(sm + 184320, sm + 193536, W2, 64, 144, tid, 256);
    float* fb = (float*)(sm + 202752);
    if (tid < 64) {
        fb[tid] = b0[tid]; fb[64 + tid] = b1[tid]; fb[128 + tid] = b2[tid];
        fb[192 + tid] = gam[tid]; fb[256 + tid] = bet[tid];
    }
    __syncthreads();

    const uint32_t aHiB[2] = { smb + wid * 4608, smb + 36864 + wid * 4608 };
    const uint32_t aLoB[2] = { smb + 73728 + wid * 4608, smb + 110592 + wid * 4608 };

    const int tq = lane >> 3;
    const int rA = (lane & 7) + ((tq & 1) << 3);
    const int kA = (tq >> 1) << 3;
    const int ofsB144 = ((tq >> 1) * 8 + (lane & 7)) * 144 + (tq & 1) * 16;
    const uint32_t b1h = smb + 147456 + ofsB144, b1l = smb + 156672 + ofsB144;
    const uint32_t b2h = smb + 165888 + ofsB144, b2l = smb + 175104 + ofsB144;
    const uint32_t b3h = smb + 184320 + ofsB144, b3l = smb + 193536 + ofsB144;

    const int g = lane >> 2, c = lane & 3;

    const int NWT = NE / 32;
    const int stride = gridDim.x * 8;
    int wt = blockIdx.x * 8 + wid;
    int buf = 0;

    if (wt < NWT) {
        const int ea = wt * 32 + lane;
        const char* seh = (const char*)(g_ehi + (size_t)ea * 64);
        const char* sel = (const char*)(g_elo + (size_t)ea * 64);
        const uint32_t dH = aHiB[0] + lane * 144, dL = aLoB[0] + lane * 144;
#pragma unroll
        for (int j = 0; j < 8; j++) {
            cpasync16(dH + j * 16, seh + j * 16);
            cpasync16(dL + j * 16, sel + j * 16);
        }
    }
    CP_COMMIT();

    for (; wt < NWT; wt += stride) {
        const int wtn = wt + stride;
        if (wtn < NWT) {
            const int ean = wtn * 32 + lane;
            const char* seh = (const char*)(g_ehi + (size_t)ean * 64);
            const char* sel = (const char*)(g_elo + (size_t)ean * 64);
            const uint32_t dH = aHiB[buf ^ 1] + lane * 144, dL = aLoB[buf ^ 1] + lane * 144;
#pragma unroll
            for (int j = 0; j < 8; j++) {
                cpasync16(dH + j * 16, seh + j * 16);
                cpasync16(dL + j * 16, sel + j * 16);
            }
            CP_COMMIT();
        }

        int sI[2][2], dI[2][2];
#pragma unroll
        for (int t = 0; t < 2; t++) {
            const int b = wt * 32 + 16 * t + g;
            sI[t][0] = __ldg(src + b); sI[t][1] = __ldg(src + b + 8);
            dI[t][0] = __ldg(dst + b); dI[t][1] = __ldg(dst + b + 8);
        }
        float d[2][8][4];
#pragma unroll
        for (int t = 0; t < 2; t++) {
            const float* ys0 = g_y + (size_t)sI[t][0] * 128;
            const float* yd0 = g_y + (size_t)dI[t][0] * 128 + 64;
            const float* ys1 = g_y + (size_t)sI[t][1] * 128;
            const float* yd1 = g_y + (size_t)dI[t][1] * 128 + 64;
#pragma unroll
            for (int nt = 0; nt < 8; nt++) {
                const int col = nt * 8 + 2 * c;
                float2 a = *(const float2*)(ys0 + col);
                float2 b = *(const float2*)(yd0 + col);
                d[t][nt][0] = a.x + b.x; d[t][nt][1] = a.y + b.y;
                a = *(const float2*)(ys1 + col);
                b = *(const float2*)(yd1 + col);
                d[t][nt][2] = a.x + b.x; d[t][nt][3] = a.y + b.y;
            }
        }

        if (wtn < NWT) { CP_WAIT1(); } else { CP_WAIT0(); }
        __syncwarp();

        const uint32_t aHi[2] = { aHiB[buf] + rA * 144 + kA * 2,
                                  aHiB[buf] + (16 + rA) * 144 + kA * 2 };
        const uint32_t aLo[2] = { aLoB[buf] + rA * 144 + kA * 2,
                                  aLoB[buf] + (16 + rA) * 144 + kA * 2 };
        layer_smemA2<4>(d, aHi, aLo, b1h, b1l, 2304);

        uint32_t aH[2][4][4], aL[2][4][4];
        inter_reg2(d, fb, c, aH, aL);
        layer_regA2(d, aH, aL, b2h, b2l, 2304);
        inter_reg2(d, fb + 64, c, aH, aL);
        layer_regA2(d, aH, aL, b3h, b3l, 2304);

        char* aHiP = sm + (buf ? 36864 : 0) + wid * 4608;
        char* aLoP = sm + 73728 + (buf ? 36864 : 0) + wid * 4608;
        const float* b2v = fb + 128;
        const float* gmp = fb + 192;
        const float* btp = fb + 256;
#pragma unroll
        for (int t = 0; t < 2; t++) {
            const int r0 = 16 * t + g;
#pragma unroll
            for (int nt = 0; nt < 8; nt++) {
                int col = nt * 8 + 2 * c;
                float2 b = *(const float2*)(b2v + col);
                d[t][nt][0] += b.x; d[t][nt][1] += b.y;
                d[t][nt][2] += b.x; d[t][nt][3] += b.y;
            }
            float s0 = 0, q0 = 0, s1 = 0, q1 = 0;
#pragma unroll
            for (int nt = 0; nt < 8; nt++) {
                s0 += d[t][nt][0] + d[t][nt][1];
                q0 += d[t][nt][0] * d[t][nt][0] + d[t][nt][1] * d[t][nt][1];
                s1 += d[t][nt][2] + d[t][nt][3];
                q1 += d[t][nt][2] * d[t][nt][2] + d[t][nt][3] * d[t][nt][3];
            }
#pragma unroll
            for (int o = 1; o <= 2; o <<= 1) {
                s0 += __shfl_xor_sync(0xffffffffu, s0, o);
                q0 += __shfl_xor_sync(0xffffffffu, q0, o);
                s1 += __shfl_xor_sync(0xffffffffu, s1, o);
                q1 += __shfl_xor_sync(0xffffffffu, q1, o);
            }
            const float mu0 = s0 * (1.f / 64.f), mu1 = s1 * (1.f / 64.f);
            const float ri0 = rsqrtf(q0 * (1.f / 64.f) - mu0 * mu0 + EPS_LN);
            const float ri1 = rsqrtf(q1 * (1.f / 64.f) - mu1 * mu1 + EPS_LN);
            const int ea0 = wt * 32 + r0, ea1 = ea0 + 8;
            float* eo0 = eout + (size_t)ea0 * 64;
            float* eo1 = eout + (size_t)ea1 * 64;
#pragma unroll
            for (int nt = 0; nt < 8; nt++) {
                int col = nt * 8 + 2 * c;
                float2 gmv = *(const float2*)(gmp + col);
                float2 btv = *(const float2*)(btp + col);
                float2 e0 = join2(*(const uint32_t*)(aHiP + r0 * 144 + col * 2),
                                  *(const uint32_t*)(aLoP + r0 * 144 + col * 2));
                float2 e1 = join2(*(const uint32_t*)(aHiP + (r0 + 8) * 144 + col * 2),
                                  *(const uint32_t*)(aLoP + (r0 + 8) * 144 + col * 2));
                float o0 = (d[t][nt][0] - mu0) * ri0 * gmv.x + btv.x + e0.x;
                float o1 = (d[t][nt][1] - mu0) * ri0 * gmv.y + btv.y + e0.y;
                float p0 = (d[t][nt][2] - mu1) * ri1 * gmv.x + btv.x + e1.x;
                float p1 = (d[t][nt][3] - mu1) * ri1 * gmv.y + btv.y + e1.y;
                // ALWAYS store the bf16 split (agg kernel consumes it)
                uint32_t hh, ll;
                split2(o0, o1, hh, ll);
                *(uint32_t*)((char*)g_ehi + ((size_t)ea0 * 64 + col) * 2) = hh;
                *(uint32_t*)((char*)g_elo + ((size_t)ea0 * 64 + col) * 2) = ll;
                split2(p0, p1, hh, ll);
                *(uint32_t*)((char*)g_ehi + ((size_t)ea1 * 64 + col) * 2) = hh;
                *(uint32_t*)((char*)g_elo + ((size_t)ea1 * 64 + col) * 2) = ll;
                if (fin) {
                    *(float2*)(eo0 + col) = make_float2(o0, o1);
                    *(float2*)(eo1 + col) = make_float2(p0, p1);
                }
            }
        }
        buf ^= 1;
    }
}

// ================= NODE KERNEL =================
#define N_SMEM 195840

__global__ void __launch_bounds__(256, 1) node_kernel(
    float* xout,
    const float* __restrict__ W0, const float* __restrict__ b0,
    const float* __restrict__ W1, const float* __restrict__ b1,
    const float* __restrict__ W2, const float* __restrict__ b2,
    const float* __restrict__ gam, const float* __restrict__ bet, int fin)
{
    extern __shared__ char sm[];
    const int tid = threadIdx.x, wid = tid >> 5, lane = tid & 31;
    const uint32_t smb = smem_u32(sm);

    stage_w(sm + 139264, sm + 148480, W0 + 64 * 64, 64, 144, tid, 256);
    stage_w(sm + 157696, sm + 166912, W1, 64, 144, tid, 256);
    stage_w(sm + 176128, sm + 185344, W2, 64, 144, tid, 256);
    float* fb = (float*)(sm + 194560);
    if (tid < 64) {
        fb[tid] = b0[tid]; fb[64 + tid] = b1[tid]; fb[128 + tid] = b2[tid];
        fb[192 + tid] = gam[tid]; fb[256 + tid] = bet[tid];
    }
    __syncthreads();

    char* aHiP = sm + wid * 8704;
    char* aLoP = sm + 69632 + wid * 8704;
    const uint32_t aHiB = smb + wid * 8704, aLoB = smb + 69632 + wid * 8704;

    const int tq = lane >> 3;
    const int rA = (lane & 7) + ((tq & 1) << 3);
    const int kA = (tq >> 1) << 3;
    const uint32_t aHi[2] = { aHiB + rA * 272 + 128 + kA * 2,
                              aHiB + (16 + rA) * 272 + 128 + kA * 2 };
    const uint32_t aLo[2] = { aLoB + rA * 272 + 128 + kA * 2,
                              aLoB + (16 + rA) * 272 + 128 + kA * 2 };
    const int ofsB144 = ((tq >> 1) * 8 + (lane & 7)) * 144 + (tq & 1) * 16;
    const uint32_t b1h = smb + 139264 + ofsB144, b1l = smb + 148480 + ofsB144;
    const uint32_t b2h = smb + 157696 + ofsB144, b2l = smb + 166912 + ofsB144;
    const uint32_t b3h = smb + 176128 + ofsB144, b3l = smb + 185344 + ofsB144;

    const int g = lane >> 2, c = lane & 3;

    const int NWT = (NN + 31) / 32;
    for (int wt = blockIdx.x * 8 + wid; wt < NWT; wt += gridDim.x * 8) {
        {
            const int n = wt * 32 + lane;
            const int nc = (n < NN) ? n : (NN - 1);
            char* dh = aHiP + lane * 272;
            char* dl = aLoP + lane * 272;
            const uint4* s0 = (const uint4*)(g_xhi + (size_t)nc * 64);
            const uint4* s1 = (const uint4*)(g_xlo + (size_t)nc * 64);
#pragma unroll
            for (int j = 0; j < 8; j++) {
                ((uint4*)dh)[j] = s0[j];
                ((uint4*)dl)[j] = s1[j];
            }
            const float4* af = (const float4*)(g_agg + (size_t)nc * 64);
#pragma unroll
            for (int j = 0; j < 16; j++) {
                float4 v = af[j];
                uint32_t h0, l0, h1, l1;
                split2(v.x, v.y, h0, l0);
                split2(v.z, v.w, h1, l1);
                ((uint2*)(dh + 128))[j] = make_uint2(h0, h1);
                ((uint2*)(dl + 128))[j] = make_uint2(l0, l1);
            }
        }
        __syncwarp();

        float d[2][8][4];
#pragma unroll
        for (int t = 0; t < 2; t++) {
            const int n0 = wt * 32 + 16 * t + g, n1 = n0 + 8;
            const int n0c = (n0 < NN) ? n0 : (NN - 1);
            const int n1c = (n1 < NN) ? n1 : (NN - 1);
            const float* y0 = g_y2 + (size_t)n0c * 64;
            const float* y1 = g_y2 + (size_t)n1c * 64;
#pragma unroll
            for (int nt = 0; nt < 8; nt++) {
                const int col = nt * 8 + 2 * c;
                float2 a = *(const float2*)(y0 + col);
                d[t][nt][0] = a.x; d[t][nt][1] = a.y;
                a = *(const float2*)(y1 + col);
                d[t][nt][2] = a.x; d[t][nt][3] = a.y;
            }
        }
        layer_smemA2<4>(d, aHi, aLo, b1h, b1l, 2304);
        uint32_t aH[2][4][4], aL[2][4][4];
        inter_reg2(d, fb, c, aH, aL);
        layer_regA2(d, aH, aL, b2h, b2l, 2304);
        inter_reg2(d, fb + 64, c, aH, aL);
        layer_regA2(d, aH, aL, b3h, b3l, 2304);

        const float* b2v = fb + 128;
        const float* gmp = fb + 192;
        const float* btp = fb + 256;
#pragma unroll
        for (int t = 0; t < 2; t++) {
            const int r0 = 16 * t + g;
#pragma unroll
            for (int nt = 0; nt < 8; nt++) {
                int col = nt * 8 + 2 * c;
                float2 b = *(const float2*)(b2v + col);
                d[t][nt][0] += b.x; d[t][nt][1] += b.y;
                d[t][nt][2] += b.x; d[t][nt][3] += b.y;
            }
            float s0 = 0, q0 = 0, s1 = 0, q1 = 0;
#pragma unroll
            for (int nt = 0; nt < 8; nt++) {
                s0 += d[t][nt][0] + d[t][nt][1];
                q0 += d[t][nt][0] * d[t][nt][0] + d[t][nt][1] * d[t][nt][1];
                s1 += d[t][nt][2] + d[t][nt][3];
                q1 += d[t][nt][2] * d[t][nt][2] + d[t][nt][3] * d[t][nt][3];
            }
#pragma unroll
            for (int o = 1; o <= 2; o <<= 1) {
                s0 += __shfl_xor_sync(0xffffffffu, s0, o);
                q0 += __shfl_xor_sync(0xffffffffu, q0, o);
                s1 += __shfl_xor_sync(0xffffffffu, s1, o);
                q1 += __shfl_xor_sync(0xffffffffu, q1, o);
            }
            const float mu0 = s0 * (1.f / 64.f), mu1 = s1 * (1.f / 64.f);
            const float ri0 = rsqrtf(q0 * (1.f / 64.f) - mu0 * mu0 + EPS_LN);
            const float ri1 = rsqrtf(q1 * (1.f / 64.f) - mu1 * mu1 + EPS_LN);
            const int n0 = wt * 32 + r0, n1 = n0 + 8;
            const bool v0 = n0 < NN, v1 = n1 < NN;
            float* xo0 = xout + (size_t)n0 * 64;
            float* xo1 = xout + (size_t)n1 * 64;
#pragma unroll
            for (int nt = 0; nt < 8; nt++) {
                int col = nt * 8 + 2 * c;
                float2 gmv = *(const float2*)(gmp + col);
                float2 btv = *(const float2*)(btp + col);
                float2 x0 = join2(*(const uint32_t*)(aHiP + r0 * 272 + col * 2),
                                  *(const uint32_t*)(aLoP + r0 * 272 + col * 2));
                float2 x1 = join2(*(const uint32_t*)(aHiP + (r0 + 8) * 272 + col * 2),
                                  *(const uint32_t*)(aLoP + (r0 + 8) * 272 + col * 2));
                float o0 = (d[t][nt][0] - mu0) * ri0 * gmv.x + btv.x + x0.x;
                float o1 = (d[t][nt][1] - mu0) * ri0 * gmv.y + btv.y + x0.y;
                float p0 = (d[t][nt][2] - mu1) * ri1 * gmv.x + btv.x + x1.x;
                float p1 = (d[t][nt][3] - mu1) * ri1 * gmv.y + btv.y + x1.y;
                if (fin) {
                    if (v0) *(float2*)(xo0 + col) = make_float2(o0, o1);
                    if (v1) *(float2*)(xo1 + col) = make_float2(p0, p1);
                } else {
                    uint32_t hh, ll;
                    if (v0) {
                        split2(o0, o1, hh, ll);
                        *(uint32_t*)((char*)g_xhi + ((size_t)n0 * 64 + col) * 2) = hh;
                        *(uint32_t*)((char*)g_xlo + ((size_t)n0 * 64 + col) * 2) = ll;
                    }
                    if (v1) {
                        split2(p0, p1, hh, ll);
                        *(uint32_t*)((char*)g_xhi + ((size_t)n1 * 64 + col) * 2) = hh;
                        *(uint32_t*)((char*)g_xlo + ((size_t)n1 * 64 + col) * 2) = ll;
                    }
                }
            }
        }
        __syncwarp();
    }
}

// ================= streaming split =================
__global__ void split_kernel(const float* __restrict__ in, __nv_bfloat16* __restrict__ hi,
                             __nv_bfloat16* __restrict__ lo, long n4) {
    for (long i = blockIdx.x * (long)blockDim.x + threadIdx.x; i < n4;
         i += (long)gridDim.x * blockDim.x) {
        float4 v = ((const float4*)in)[i];
        uint32_t h0, l0, h1, l1;
        split2(v.x, v.y, h0, l0);
        split2(v.z, v.w, h1, l1);
        ((uint2*)hi)[i] = make_uint2(h0, h1);
        ((uint2*)lo)[i] = make_uint2(l0, l1);
    }
}

// ================= launcher =================
extern "C" void kernel_launch(void* const* d_in, const int* in_sizes, int n_in,
                              void* d_out, int out_size) {
    const float* x_in = (const float*)d_in[0];
    const float* e_in = (const float*)d_in[1];
    const int* ei = (const int*)d_in[2];
    const int *src = ei, *dst = ei + NE;
    const float* ew0 = (const float*)d_in[3];  const float* eb0 = (const float*)d_in[4];
    const float* ew1 = (const float*)d_in[5];  const float* eb1 = (const float*)d_in[6];
    const float* ew2 = (const float*)d_in[7];  const float* eb2 = (const float*)d_in[8];
    const float* eg  = (const float*)d_in[9];  const float* ebt = (const float*)d_in[10];
    const float* nw0 = (const float*)d_in[11]; const float* nb0 = (const float*)d_in[12];
    const float* nw1 = (const float*)d_in[13]; const float* nb1 = (const float*)d_in[14];
    const float* nw2 = (const float*)d_in[15]; const float* nb2 = (const float*)d_in[16];
    const float* ng  = (const float*)d_in[17]; const float* nbt = (const float*)d_in[18];

    float* out_x = (float*)d_out;
    float* out_e = (float*)d_out + (size_t)NN * 64;

    __nv_bfloat16 *xhi, *xlo, *ehi, *elo;
    cudaGetSymbolAddress((void**)&xhi, g_xhi);
    cudaGetSymbolAddress((void**)&xlo, g_xlo);
    cudaGetSymbolAddress((void**)&ehi, g_ehi);
    cudaGetSymbolAddress((void**)&elo, g_elo);

    cudaFuncSetAttribute(edge_kernel, cudaFuncAttributeMaxDynamicSharedMemorySize, E_SMEM);
    cudaFuncSetAttribute(node_kernel, cudaFuncAttributeMaxDynamicSharedMemorySize, N_SMEM);
    cudaFuncSetAttribute(node_pre_kernel, cudaFuncAttributeMaxDynamicSharedMemorySize, PRE_SMEM);

    // CSR build (edge_index constant across layers)
    build_zero<<<128, 256>>>();
    build_hist<<<512, 256>>>(dst);
    build_scan<<<1, 1024>>>();
    build_fill<<<512, 256>>>(dst);

    split_kernel<<<512, 256>>>(x_in, xhi, xlo, (long)NN * 16);
    split_kernel<<<1024, 256>>>(e_in, ehi, elo, (long)NE * 16);

    const int EW0S = 192 * 64, EWS = 64 * 64, NW0S = 128 * 64;
    for (int i = 0; i < 3; i++) {
        const int fin = (i == 2) ? 1 : 0;
        node_pre_kernel<<<148, 256, PRE_SMEM>>>(ew0 + i * EW0S, nw0 + i * NW0S);
        edge_kernel<<<148, 256, E_SMEM>>>(
            out_e, src, dst,
            ew0 + i * EW0S, eb0 + i * 64, ew1 + i * EWS, eb1 + i * 64,
            ew2 + i * EWS, eb2 + i * 64, eg + i * 64, ebt + i * 64, fin);
        agg_kernel<<<1024, 256>>>();
        node_kernel<<<148, 256, N_SMEM>>>(
            out_x,
            nw0 + i * NW0S, nb0 + i * 64, nw1 + i * EWS, nb1 + i * 64,
            nw2 + i * EWS, nb2 + i * 64, ng + i * 64, nbt + i * 64, fin);
    }
}

// round 14
// speedup vs baseline: 1.2142x; 1.2142x over previous
#include <cuda_runtime.h>
#include <cuda_bf16.h>
#include <cstdint>

#define NN 50000
#define NE 800000
#define EPS_LN 1e-5f

// ---------------- scratch (no allocations allowed) ----------------
__device__ __align__(128) float g_agg[NN * 64];
__device__ __align__(128) float g_y[(size_t)NN * 128];   // edge-layer node partials
__device__ __align__(128) __nv_bfloat16 g_xhi[NN * 64], g_xlo[NN * 64];
__device__ __align__(128) __nv_bfloat16 g_ehi[(size_t)NE * 64], g_elo[(size_t)NE * 64];

// ---------------- helpers ----------------
__device__ __forceinline__ uint32_t smem_u32(const void* p) {
    uint32_t a;
    asm("{ .reg .u64 t; cvta.to.shared.u64 t, %1; cvt.u32.u64 %0, t; }" : "=r"(a) : "l"(p));
    return a;
}
__device__ __forceinline__ void split2(float f0, float f1, uint32_t& hi, uint32_t& lo) {
    uint32_t h;
    asm("cvt.rn.bf16x2.f32 %0, %1, %2;" : "=r"(h) : "f"(f1), "f"(f0));
    float h0 = __uint_as_float(h << 16);
    float h1 = __uint_as_float(h & 0xFFFF0000u);
    asm("cvt.rn.bf16x2.f32 %0, %1, %2;" : "=r"(lo) : "f"(f1 - h1), "f"(f0 - h0));
    hi = h;
}
__device__ __forceinline__ float2 join2(uint32_t hh, uint32_t ll) {
    float2 v;
    v.x = __uint_as_float(hh << 16) + __uint_as_float(ll << 16);
    v.y = __uint_as_float(hh & 0xFFFF0000u) + __uint_as_float(ll & 0xFFFF0000u);
    return v;
}
__device__ __forceinline__ void red2(float* p, float a, float b) {
    asm volatile("red.global.add.v2.f32 [%0], {%1, %2};" :: "l"(p), "f"(a), "f"(b) : "memory");
}
__device__ __forceinline__ void ldm4(uint32_t r[4], uint32_t a) {
    asm volatile("ldmatrix.sync.aligned.m8n8.x4.shared.b16 {%0,%1,%2,%3}, [%4];"
                 : "=r"(r[0]), "=r"(r[1]), "=r"(r[2]), "=r"(r[3]) : "r"(a));
}
__device__ __forceinline__ void mma16816(float d[4], const uint32_t a[4],
                                         uint32_t b0, uint32_t b1) {
    asm volatile("mma.sync.aligned.m16n8k16.row.col.f32.bf16.bf16.f32 "
                 "{%0,%1,%2,%3},{%4,%5,%6,%7},{%8,%9},{%0,%1,%2,%3};"
                 : "+f"(d[0]), "+f"(d[1]), "+f"(d[2]), "+f"(d[3])
                 : "r"(a[0]), "r"(a[1]), "r"(a[2]), "r"(a[3]), "r"(b0), "r"(b1));
}
__device__ __forceinline__ void cpasync16(uint32_t dst, const void* src) {
    asm volatile("cp.async.ca.shared.global [%0], [%1], 16;" :: "r"(dst), "l"(src));
}
#define CP_COMMIT() asm volatile("cp.async.commit_group;" ::: "memory")
#define CP_WAIT0()  asm volatile("cp.async.wait_group 0;" ::: "memory")
#define CP_WAIT1()  asm volatile("cp.async.wait_group 1;" ::: "memory")

// ---- A from smem, TWO m16 tiles share B; caller initializes d ----
template <int KT>
__device__ __forceinline__ void layer_smemA2(float (&d)[2][8][4],
        const uint32_t (&aHi)[2], const uint32_t (&aLo)[2],
        uint32_t bHi, uint32_t bLo, int bstep) {
#pragma unroll
    for (int kt = 0; kt < KT; kt++) {
        uint32_t ah[2][4], al[2][4];
        ldm4(ah[0], aHi[0] + kt * 32); ldm4(al[0], aLo[0] + kt * 32);
        ldm4(ah[1], aHi[1] + kt * 32); ldm4(al[1], aLo[1] + kt * 32);
        uint32_t bh[4][4], bl[4][4];
#pragma unroll
        for (int np = 0; np < 4; np++) {
            ldm4(bh[np], bHi + np * bstep + kt * 32);
            ldm4(bl[np], bLo + np * bstep + kt * 32);
        }
#pragma unroll
        for (int np = 0; np < 4; np++)
#pragma unroll
            for (int t = 0; t < 2; t++) {
                mma16816(d[t][2 * np],     ah[t], bh[np][0], bh[np][1]);
                mma16816(d[t][2 * np + 1], ah[t], bh[np][2], bh[np][3]);
            }
#pragma unroll
        for (int np = 0; np < 4; np++)
#pragma unroll
            for (int t = 0; t < 2; t++) {
                mma16816(d[t][2 * np],     ah[t], bl[np][0], bl[np][1]);
                mma16816(d[t][2 * np + 1], ah[t], bl[np][2], bl[np][3]);
            }
#pragma unroll
        for (int np = 0; np < 4; np++)
#pragma unroll
            for (int t = 0; t < 2; t++) {
                mma16816(d[t][2 * np],     al[t], bh[np][0], bh[np][1]);
                mma16816(d[t][2 * np + 1], al[t], bh[np][2], bh[np][3]);
            }
    }
}

// ---- A in registers (K=64), two tiles share B ----
__device__ __forceinline__ void layer_regA2(float (&d)[2][8][4],
        const uint32_t (&aH)[2][4][4], const uint32_t (&aL)[2][4][4],
        uint32_t bHi, uint32_t bLo, int bstep) {
#pragma unroll
    for (int t = 0; t < 2; t++)
#pragma unroll
        for (int nt = 0; nt < 8; nt++)
            d[t][nt][0] = d[t][nt][1] = d[t][nt][2] = d[t][nt][3] = 0.f;
#pragma unroll
    for (int kt = 0; kt < 4; kt++) {
        uint32_t bh[4][4], bl[4][4];
#pragma unroll
        for (int np = 0; np < 4; np++) {
            ldm4(bh[np], bHi + np * bstep + kt * 32);
            ldm4(bl[np], bLo + np * bstep + kt * 32);
        }
#pragma unroll
        for (int np = 0; np < 4; np++)
#pragma unroll
            for (int t = 0; t < 2; t++) {
                mma16816(d[t][2 * np],     aH[t][kt], bh[np][0], bh[np][1]);
                mma16816(d[t][2 * np + 1], aH[t][kt], bh[np][2], bh[np][3]);
            }
#pragma unroll
        for (int np = 0; np < 4; np++)
#pragma unroll
            for (int t = 0; t < 2; t++) {
                mma16816(d[t][2 * np],     aH[t][kt], bl[np][0], bl[np][1]);
                mma16816(d[t][2 * np + 1], aH[t][kt], bl[np][2], bl[np][3]);
            }
#pragma unroll
        for (int np = 0; np < 4; np++)
#pragma unroll
            for (int t = 0; t < 2; t++) {
                mma16816(d[t][2 * np],     aL[t][kt], bh[np][0], bh[np][1]);
                mma16816(d[t][2 * np + 1], aL[t][kt], bh[np][2], bh[np][3]);
            }
    }
}

// accumulator fragments -> next-layer A fragments, in registers
__device__ __forceinline__ void inter_reg2(const float (&d)[2][8][4], const float* bias, int c,
                                           uint32_t (&aH)[2][4][4], uint32_t (&aL)[2][4][4]) {
#pragma unroll
    for (int t = 0; t < 2; t++)
#pragma unroll
        for (int kt = 0; kt < 4; kt++) {
            float2 b0 = *(const float2*)(bias + 16 * kt + 2 * c);
            split2(fmaxf(d[t][2 * kt][0] + b0.x, 0.f), fmaxf(d[t][2 * kt][1] + b0.y, 0.f),
                   aH[t][kt][0], aL[t][kt][0]);
            split2(fmaxf(d[t][2 * kt][2] + b0.x, 0.f), fmaxf(d[t][2 * kt][3] + b0.y, 0.f),
                   aH[t][kt][1], aL[t][kt][1]);
            float2 b1 = *(const float2*)(bias + 16 * kt + 8 + 2 * c);
            split2(fmaxf(d[t][2 * kt + 1][0] + b1.x, 0.f), fmaxf(d[t][2 * kt + 1][1] + b1.y, 0.f),
                   aH[t][kt][2], aL[t][kt][2]);
            split2(fmaxf(d[t][2 * kt + 1][2] + b1.x, 0.f), fmaxf(d[t][2 * kt + 1][3] + b1.y, 0.f),
                   aH[t][kt][3], aL[t][kt][3]);
        }
}

// stage W[k][n] (row-major) as B[n][k] hi/lo with row stride bstr bytes
__device__ __forceinline__ void stage_w(char* dsth, char* dstl, const float* W,
                                        int K, int bstr, int tid, int nthr) {
    for (int idx = tid; idx < K * 64; idx += nthr) {
        int k = idx >> 6, n = idx & 63;
        float f = W[idx];
        __nv_bfloat16 h = __float2bfloat16_rn(f);
        __nv_bfloat16 l = __float2bfloat16_rn(f - __bfloat162float(h));
        int off = n * bstr + k * 2;
        *(__nv_bfloat16*)(dsth + off) = h;
        *(__nv_bfloat16*)(dstl + off) = l;
    }
}

// ================= NODE-PARTIAL PRECOMPUTE (MMA) + agg zero =================
// y[n][j] = sum_k x[n][k] * W0[k + 64*(j>=64)][j&63]   (3-pass bf16)
#define PRE_SMEM 110592

__global__ void __launch_bounds__(256, 1) node_pre_kernel(const float* __restrict__ W0) {
    extern __shared__ char sm[];
    const int tid = threadIdx.x, wid = tid >> 5, lane = tid & 31;
    const uint32_t smb = smem_u32(sm);

    // fused: zero the aggregation buffer (was a separate kernel)
    for (int i = blockIdx.x * blockDim.x + tid; i < NN * 16; i += gridDim.x * blockDim.x)
        ((float4*)g_agg)[i] = make_float4(0.f, 0.f, 0.f, 0.f);

    // stage Bcat[j][k] = W0[k + 64*(j>=64)][j&63]
    for (int idx = tid; idx < 128 * 64; idx += 256) {
        int j = idx >> 6, k = idx & 63;
        float f = W0[(k + ((j >= 64) ? 64 : 0)) * 64 + (j & 63)];
        __nv_bfloat16 h = __float2bfloat16_rn(f);
        __nv_bfloat16 l = __float2bfloat16_rn(f - __bfloat162float(h));
        int off = j * 144 + k * 2;
        *(__nv_bfloat16*)(sm + 73728 + off) = h;
        *(__nv_bfloat16*)(sm + 92160 + off) = l;
    }
    __syncthreads();

    char* aHiP = sm + wid * 4608;
    char* aLoP = sm + 36864 + wid * 4608;
    const uint32_t aHiB = smb + wid * 4608, aLoB = smb + 36864 + wid * 4608;

    const int tq = lane >> 3;
    const int rA = (lane & 7) + ((tq & 1) << 3);
    const int kA = (tq >> 1) << 3;
    const uint32_t aHi[2] = { aHiB + rA * 144 + kA * 2, aHiB + (16 + rA) * 144 + kA * 2 };
    const uint32_t aLo[2] = { aLoB + rA * 144 + kA * 2, aLoB + (16 + rA) * 144 + kA * 2 };
    const int ofsB144 = ((tq >> 1) * 8 + (lane & 7)) * 144 + (tq & 1) * 16;
    const uint32_t bh = smb + 73728 + ofsB144, bl = smb + 92160 + ofsB144;

    const int g = lane >> 2, c = lane & 3;

    const int NWT = (NN + 31) / 32;
    for (int wt = blockIdx.x * 8 + wid; wt < NWT; wt += gridDim.x * 8) {
        {
            const int n = wt * 32 + lane;
            const int nc = (n < NN) ? n : (NN - 1);
            const uint4* s0 = (const uint4*)(g_xhi + (size_t)nc * 64);
            const uint4* s1 = (const uint4*)(g_xlo + (size_t)nc * 64);
            uint4* dh = (uint4*)(aHiP + lane * 144);
            uint4* dl = (uint4*)(aLoP + lane * 144);
#pragma unroll
            for (int j = 0; j < 8; j++) { dh[j] = s0[j]; dl[j] = s1[j]; }
        }
        __syncwarp();

#pragma unroll
        for (int half = 0; half < 2; half++) {
            float d[2][8][4];
#pragma unroll
            for (int t = 0; t < 2; t++)
#pragma unroll
                for (int nt = 0; nt < 8; nt++)
                    d[t][nt][0] = d[t][nt][1] = d[t][nt][2] = d[t][nt][3] = 0.f;
            layer_smemA2<4>(d, aHi, aLo, bh + half * 4 * 2304, bl + half * 4 * 2304, 2304);
#pragma unroll
            for (int t = 0; t < 2; t++) {
                const int n0 = wt * 32 + 16 * t + g, n1 = n0 + 8;
                const bool v0 = n0 < NN, v1 = n1 < NN;
#pragma unroll
                for (int nt = 0; nt < 8; nt++) {
                    const int col = nt * 8 + 2 * c;
                    if (v0) *(float2*)(g_y + (size_t)n0 * 128 + half * 64 + col)
                                = make_float2(d[t][nt][0], d[t][nt][1]);
                    if (v1) *(float2*)(g_y + (size_t)n1 * 128 + half * 64 + col)
                                = make_float2(d[t][nt][2], d[t][nt][3]);
                }
            }
        }
        __syncwarp();
    }
}

// ================= EDGE KERNEL =================
// 8 warps x 32 rows. A holds ONLY e (64 cols, stride 144 B), double-buffered.
#define E_SMEM 204032

__global__ void __launch_bounds__(256, 1) edge_kernel(
    float* eout,
    const int* __restrict__ src, const int* __restrict__ dst,
    const float* __restrict__ W0, const float* __restrict__ b0,
    const float* __restrict__ W1, const float* __restrict__ b1,
    const float* __restrict__ W2, const float* __restrict__ b2,
    const float* __restrict__ gam, const float* __restrict__ bet, int fin)
{
    extern __shared__ char sm[];
    const int tid = threadIdx.x, wid = tid >> 5, lane = tid & 31;
    const uint32_t smb = smem_u32(sm);

    stage_w(sm + 147456, sm + 156672, W0 + 128 * 64, 64, 144, tid, 256);  // e-part of W0
    stage_w(sm + 165888, sm + 175104, W1, 64, 144, tid, 256);
    stage_w(sm + 184320, sm + 193536, W2, 64, 144, tid, 256);
    float* fb = (float*)(sm + 202752);
    if (tid < 64) {
        fb[tid] = b0[tid]; fb[64 + tid] = b1[tid]; fb[128 + tid] = b2[tid];
        fb[192 + tid] = gam[tid]; fb[256 + tid] = bet[tid];
    }
    __syncthreads();

    const uint32_t aHiB[2] = { smb + wid * 4608, smb + 36864 + wid * 4608 };
    const uint32_t aLoB[2] = { smb + 73728 + wid * 4608, smb + 110592 + wid * 4608 };

    const int tq = lane >> 3;
    const int rA = (lane & 7) + ((tq & 1) << 3);
    const int kA = (tq >> 1) << 3;
    const int ofsB144 = ((tq >> 1) * 8 + (lane & 7)) * 144 + (tq & 1) * 16;
    const uint32_t b1h = smb + 147456 + ofsB144, b1l = smb + 156672 + ofsB144;
    const uint32_t b2h = smb + 165888 + ofsB144, b2l = smb + 175104 + ofsB144;
    const uint32_t b3h = smb + 184320 + ofsB144, b3l = smb + 193536 + ofsB144;

    const int g = lane >> 2, c = lane & 3;

    const int NWT = NE / 32;
    const int stride = gridDim.x * 8;
    int wt = blockIdx.x * 8 + wid;
    int buf = 0;

    if (wt < NWT) {
        const int ea = wt * 32 + lane;
        const char* seh = (const char*)(g_ehi + (size_t)ea * 64);
        const char* sel = (const char*)(g_elo + (size_t)ea * 64);
        const uint32_t dH = aHiB[0] + lane * 144, dL = aLoB[0] + lane * 144;
#pragma unroll
        for (int j = 0; j < 8; j++) {
            cpasync16(dH + j * 16, seh + j * 16);
            cpasync16(dL + j * 16, sel + j * 16);
        }
    }
    CP_COMMIT();

    for (; wt < NWT; wt += stride) {
        const int wtn = wt + stride;
        if (wtn < NWT) {
            const int ean = wtn * 32 + lane;
            const char* seh = (const char*)(g_ehi + (size_t)ean * 64);
            const char* sel = (const char*)(g_elo + (size_t)ean * 64);
            const uint32_t dH = aHiB[buf ^ 1] + lane * 144, dL = aLoB[buf ^ 1] + lane * 144;
#pragma unroll
            for (int j = 0; j < 8; j++) {
                cpasync16(dH + j * 16, seh + j * 16);
                cpasync16(dL + j * 16, sel + j * 16);
            }
            CP_COMMIT();
        }

        int sI[2][2], dI[2][2];
#pragma unroll
        for (int t = 0; t < 2; t++) {
            const int b = wt * 32 + 16 * t + g;
            sI[t][0] = __ldg(src + b); sI[t][1] = __ldg(src + b + 8);
            dI[t][0] = __ldg(dst + b); dI[t][1] = __ldg(dst + b + 8);
        }
        float d[2][8][4];
#pragma unroll
        for (int t = 0; t < 2; t++) {
            const float* ys0 = g_y + (size_t)sI[t][0] * 128;
            const float* yd0 = g_y + (size_t)dI[t][0] * 128 + 64;
            const float* ys1 = g_y + (size_t)sI[t][1] * 128;
            const float* yd1 = g_y + (size_t)dI[t][1] * 128 + 64;
#pragma unroll
            for (int nt = 0; nt < 8; nt++) {
                const int col = nt * 8 + 2 * c;
                float2 a = *(const float2*)(ys0 + col);
                float2 b = *(const float2*)(yd0 + col);
                d[t][nt][0] = a.x + b.x; d[t][nt][1] = a.y + b.y;
                a = *(const float2*)(ys1 + col);
                b = *(const float2*)(yd1 + col);
                d[t][nt][2] = a.x + b.x; d[t][nt][3] = a.y + b.y;
            }
        }

        if (wtn < NWT) { CP_WAIT1(); } else { CP_WAIT0(); }
        __syncwarp();

        const uint32_t aHi[2] = { aHiB[buf] + rA * 144 + kA * 2,
                                  aHiB[buf] + (16 + rA) * 144 + kA * 2 };
        const uint32_t aLo[2] = { aLoB[buf] + rA * 144 + kA * 2,
                                  aLoB[buf] + (16 + rA) * 144 + kA * 2 };
        layer_smemA2<4>(d, aHi, aLo, b1h, b1l, 2304);

        uint32_t aH[2][4][4], aL[2][4][4];
        inter_reg2(d, fb, c, aH, aL);
        layer_regA2(d, aH, aL, b2h, b2l, 2304);
        inter_reg2(d, fb + 64, c, aH, aL);
        layer_regA2(d, aH, aL, b3h, b3l, 2304);

        char* aHiP = sm + (buf ? 36864 : 0) + wid * 4608;
        char* aLoP = sm + 73728 + (buf ? 36864 : 0) + wid * 4608;
        const float* b2v = fb + 128;
        const float* gmp = fb + 192;
        const float* btp = fb + 256;
#pragma unroll
        for (int t = 0; t < 2; t++) {
            const int r0 = 16 * t + g;
#pragma unroll
            for (int nt = 0; nt < 8; nt++) {
                int col = nt * 8 + 2 * c;
                float2 b = *(const float2*)(b2v + col);
                d[t][nt][0] += b.x; d[t][nt][1] += b.y;
                d[t][nt][2] += b.x; d[t][nt][3] += b.y;
            }
            float s0 = 0, q0 = 0, s1 = 0, q1 = 0;
#pragma unroll
            for (int nt = 0; nt < 8; nt++) {
                s0 += d[t][nt][0] + d[t][nt][1];
                q0 += d[t][nt][0] * d[t][nt][0] + d[t][nt][1] * d[t][nt][1];
                s1 += d[t][nt][2] + d[t][nt][3];
                q1 += d[t][nt][2] * d[t][nt][2] + d[t][nt][3] * d[t][nt][3];
            }
#pragma unroll
            for (int o = 1; o <= 2; o <<= 1) {
                s0 += __shfl_xor_sync(0xffffffffu, s0, o);
                q0 += __shfl_xor_sync(0xffffffffu, q0, o);
                s1 += __shfl_xor_sync(0xffffffffu, s1, o);
                q1 += __shfl_xor_sync(0xffffffffu, q1, o);
            }
            const float mu0 = s0 * (1.f / 64.f), mu1 = s1 * (1.f / 64.f);
            const float ri0 = rsqrtf(q0 * (1.f / 64.f) - mu0 * mu0 + EPS_LN);
            const float ri1 = rsqrtf(q1 * (1.f / 64.f) - mu1 * mu1 + EPS_LN);
            const int ea0 = wt * 32 + r0, ea1 = ea0 + 8;
            float* eo0 = eout + (size_t)ea0 * 64;
            float* eo1 = eout + (size_t)ea1 * 64;
            float* ag0 = g_agg + (size_t)dI[t][0] * 64;
            float* ag1 = g_agg + (size_t)dI[t][1] * 64;
#pragma unroll
            for (int nt = 0; nt < 8; nt++) {
                int col = nt * 8 + 2 * c;
                float2 gmv = *(const float2*)(gmp + col);
                float2 btv = *(const float2*)(btp + col);
                float2 e0 = join2(*(const uint32_t*)(aHiP + r0 * 144 + col * 2),
                                  *(const uint32_t*)(aLoP + r0 * 144 + col * 2));
                float2 e1 = join2(*(const uint32_t*)(aHiP + (r0 + 8) * 144 + col * 2),
                                  *(const uint32_t*)(aLoP + (r0 + 8) * 144 + col * 2));
                float o0 = (d[t][nt][0] - mu0) * ri0 * gmv.x + btv.x + e0.x;
                float o1 = (d[t][nt][1] - mu0) * ri0 * gmv.y + btv.y + e0.y;
                float p0 = (d[t][nt][2] - mu1) * ri1 * gmv.x + btv.x + e1.x;
                float p1 = (d[t][nt][3] - mu1) * ri1 * gmv.y + btv.y + e1.y;
                red2(ag0 + col, o0, o1);
                red2(ag1 + col, p0, p1);
                if (fin) {
                    *(float2*)(eo0 + col) = make_float2(o0, o1);
                    *(float2*)(eo1 + col) = make_float2(p0, p1);
                } else {
                    uint32_t hh, ll;
                    split2(o0, o1, hh, ll);
                    *(uint32_t*)((char*)g_ehi + ((size_t)ea0 * 64 + col) * 2) = hh;
                    *(uint32_t*)((char*)g_elo + ((size_t)ea0 * 64 + col) * 2) = ll;
                    split2(p0, p1, hh, ll);
                    *(uint32_t*)((char*)g_ehi + ((size_t)ea1 * 64 + col) * 2) = hh;
                    *(uint32_t*)((char*)g_elo + ((size_t)ea1 * 64 + col) * 2) = ll;
                }
            }
        }
        buf ^= 1;
    }
}

// ================= NODE KERNEL =================
// 8 warps x 32 rows. A row stride 272 B, K=128 over [x | agg].
#define N_SMEM 212224

__global__ void __launch_bounds__(256, 1) node_kernel(
    float* xout,
    const float* __restrict__ W0, const float* __restrict__ b0,
    const float* __restrict__ W1, const float* __restrict__ b1,
    const float* __restrict__ W2, const float* __restrict__ b2,
    const float* __restrict__ gam, const float* __restrict__ bet, int fin)
{
    extern __shared__ char sm[];
    const int tid = threadIdx.x, wid = tid >> 5, lane = tid & 31;
    const uint32_t smb = smem_u32(sm);

    stage_w(sm + 139264, sm + 156672, W0, 128, 272, tid, 256);
    stage_w(sm + 174080, sm + 183296, W1, 64, 144, tid, 256);
    stage_w(sm + 192512, sm + 201728, W2, 64, 144, tid, 256);
    float* fb = (float*)(sm + 210944);
    if (tid < 64) {
        fb[tid] = b0[tid]; fb[64 + tid] = b1[tid]; fb[128 + tid] = b2[tid];
        fb[192 + tid] = gam[tid]; fb[256 + tid] = bet[tid];
    }
    __syncthreads();

    char* aHiP = sm + wid * 8704;
    char* aLoP = sm + 69632 + wid * 8704;
    const uint32_t aHiB = smb + wid * 8704, aLoB = smb + 69632 + wid * 8704;

    const int tq = lane >> 3;
    const int rA = (lane & 7) + ((tq & 1) << 3);
    const int kA = (tq >> 1) << 3;
    const uint32_t aHi[2] = { aHiB + rA * 272 + kA * 2, aHiB + (16 + rA) * 272 + kA * 2 };
    const uint32_t aLo[2] = { aLoB + rA * 272 + kA * 2, aLoB + (16 + rA) * 272 + kA * 2 };
    const int ofsB272 = ((tq >> 1) * 8 + (lane & 7)) * 272 + (tq & 1) * 16;
    const int ofsB144 = ((tq >> 1) * 8 + (lane & 7)) * 144 + (tq & 1) * 16;
    const uint32_t b1h = smb + 139264 + ofsB272, b1l = smb + 156672 + ofsB272;
    const uint32_t b2h = smb + 174080 + ofsB144, b2l = smb + 183296 + ofsB144;
    const uint32_t b3h = smb + 192512 + ofsB144, b3l = smb + 201728 + ofsB144;

    const int g = lane >> 2, c = lane & 3;

    const int NWT = (NN + 31) / 32;
    for (int wt = blockIdx.x * 8 + wid; wt < NWT; wt += gridDim.x * 8) {
        {
            const int n = wt * 32 + lane;
            const int nc = (n < NN) ? n : (NN - 1);
            char* dh = aHiP + lane * 272;
            char* dl = aLoP + lane * 272;
            const uint4* s0 = (const uint4*)(g_xhi + (size_t)nc * 64);
            const uint4* s1 = (const uint4*)(g_xlo + (size_t)nc * 64);
#pragma unroll
            for (int j = 0; j < 8; j++) {
                ((uint4*)dh)[j] = s0[j];
                ((uint4*)dl)[j] = s1[j];
            }
            const float4* af = (const float4*)(g_agg + (size_t)nc * 64);
#pragma unroll
            for (int j = 0; j < 16; j++) {
                float4 v = af[j];
                uint32_t h0, l0, h1, l1;
                split2(v.x, v.y, h0, l0);
                split2(v.z, v.w, h1, l1);
                ((uint2*)(dh + 128))[j] = make_uint2(h0, h1);
                ((uint2*)(dl + 128))[j] = make_uint2(l0, l1);
            }
        }
        __syncwarp();

        float d[2][8][4];
#pragma unroll
        for (int t = 0; t < 2; t++)
#pragma unroll
            for (int nt = 0; nt < 8; nt++)
                d[t][nt][0] = d[t][nt][1] = d[t][nt][2] = d[t][nt][3] = 0.f;
        layer_smemA2<8>(d, aHi, aLo, b1h, b1l, 4352);
        uint32_t aH[2][4][4], aL[2][4][4];
        inter_reg2(d, fb, c, aH, aL);
        layer_regA2(d, aH, aL, b2h, b2l, 2304);
        inter_reg2(d, fb + 64, c, aH, aL);
        layer_regA2(d, aH, aL, b3h, b3l, 2304);

        const float* b2v = fb + 128;
        const float* gmp = fb + 192;
        const float* btp = fb + 256;
#pragma unroll
        for (int t = 0; t < 2; t++) {
            const int r0 = 16 * t + g;
#pragma unroll
            for (int nt = 0; nt < 8; nt++) {
                int col = nt * 8 + 2 * c;
                float2 b = *(const float2*)(b2v + col);
                d[t][nt][0] += b.x; d[t][nt][1] += b.y;
                d[t][nt][2] += b.x; d[t][nt][3] += b.y;
            }
            float s0 = 0, q0 = 0, s1 = 0, q1 = 0;
#pragma unroll
            for (int nt = 0; nt < 8; nt++) {
                s0 += d[t][nt][0] + d[t][nt][1];
                q0 += d[t][nt][0] * d[t][nt][0] + d[t][nt][1] * d[t][nt][1];
                s1 += d[t][nt][2] + d[t][nt][3];
                q1 += d[t][nt][2] * d[t][nt][2] + d[t][nt][3] * d[t][nt][3];
            }
#pragma unroll
            for (int o = 1; o <= 2; o <<= 1) {
                s0 += __shfl_xor_sync(0xffffffffu, s0, o);
                q0 += __shfl_xor_sync(0xffffffffu, q0, o);
                s1 += __shfl_xor_sync(0xffffffffu, s1, o);
                q1 += __shfl_xor_sync(0xffffffffu, q1, o);
            }
            const float mu0 = s0 * (1.f / 64.f), mu1 = s1 * (1.f / 64.f);
            const float ri0 = rsqrtf(q0 * (1.f / 64.f) - mu0 * mu0 + EPS_LN);
            const float ri1 = rsqrtf(q1 * (1.f / 64.f) - mu1 * mu1 + EPS_LN);
            const int n0 = wt * 32 + r0, n1 = n0 + 8;
            const bool v0 = n0 < NN, v1 = n1 < NN;
            float* xo0 = xout + (size_t)n0 * 64;
            float* xo1 = xout + (size_t)n1 * 64;
#pragma unroll
            for (int nt = 0; nt < 8; nt++) {
                int col = nt * 8 + 2 * c;
                float2 gmv = *(const float2*)(gmp + col);
                float2 btv = *(const float2*)(btp + col);
                float2 x0 = join2(*(const uint32_t*)(aHiP + r0 * 272 + col * 2),
                                  *(const uint32_t*)(aLoP + r0 * 272 + col * 2));
                float2 x1 = join2(*(const uint32_t*)(aHiP + (r0 + 8) * 272 + col * 2),
                                  *(const uint32_t*)(aLoP + (r0 + 8) * 272 + col * 2));
                float o0 = (d[t][nt][0] - mu0) * ri0 * gmv.x + btv.x + x0.x;
                float o1 = (d[t][nt][1] - mu0) * ri0 * gmv.y + btv.y + x0.y;
                float p0 = (d[t][nt][2] - mu1) * ri1 * gmv.x + btv.x + x1.x;
                float p1 = (d[t][nt][3] - mu1) * ri1 * gmv.y + btv.y + x1.y;
                if (fin) {
                    if (v0) *(float2*)(xo0 + col) = make_float2(o0, o1);
                    if (v1) *(float2*)(xo1 + col) = make_float2(p0, p1);
                } else {
                    uint32_t hh, ll;
                    if (v0) {
                        split2(o0, o1, hh, ll);
                        *(uint32_t*)((char*)g_xhi + ((size_t)n0 * 64 + col) * 2) = hh;
                        *(uint32_t*)((char*)g_xlo + ((size_t)n0 * 64 + col) * 2) = ll;
                    }
                    if (v1) {
                        split2(p0, p1, hh, ll);
                        *(uint32_t*)((char*)g_xhi + ((size_t)n1 * 64 + col) * 2) = hh;
                        *(uint32_t*)((char*)g_xlo + ((size_t)n1 * 64 + col) * 2) = ll;
                    }
                }
            }
        }
        __syncwarp();
    }
}

// ================= streaming split =================
__global__ void split_kernel(const float* __restrict__ in, __nv_bfloat16* __restrict__ hi,
                             __nv_bfloat16* __restrict__ lo, long n4) {
    for (long i = blockIdx.x * (long)blockDim.x + threadIdx.x; i < n4;
         i += (long)gridDim.x * blockDim.x) {
        float4 v = ((const float4*)in)[i];
        uint32_t h0, l0, h1, l1;
        split2(v.x, v.y, h0, l0);
        split2(v.z, v.w, h1, l1);
        ((uint2*)hi)[i] = make_uint2(h0, h1);
        ((uint2*)lo)[i] = make_uint2(l0, l1);
    }
}

// ================= launcher =================
extern "C" void kernel_launch(void* const* d_in, const int* in_sizes, int n_in,
                              void* d_out, int out_size) {
    const float* x_in = (const float*)d_in[0];
    const float* e_in = (const float*)d_in[1];
    const int* ei = (const int*)d_in[2];
    const int *src = ei, *dst = ei + NE;
    const float* ew0 = (const float*)d_in[3];  const float* eb0 = (const float*)d_in[4];
    const float* ew1 = (const float*)d_in[5];  const float* eb1 = (const float*)d_in[6];
    const float* ew2 = (const float*)d_in[7];  const float* eb2 = (const float*)d_in[8];
    const float* eg  = (const float*)d_in[9];  const float* ebt = (const float*)d_in[10];
    const float* nw0 = (const float*)d_in[11]; const float* nb0 = (const float*)d_in[12];
    const float* nw1 = (const float*)d_in[13]; const float* nb1 = (const float*)d_in[14];
    const float* nw2 = (const float*)d_in[15]; const float* nb2 = (const float*)d_in[16];
    const float* ng  = (const float*)d_in[17]; const float* nbt = (const float*)d_in[18];

    float* out_x = (float*)d_out;
    float* out_e = (float*)d_out + (size_t)NN * 64;

    __nv_bfloat16 *xhi, *xlo, *ehi, *elo;
    cudaGetSymbolAddress((void**)&xhi, g_xhi);
    cudaGetSymbolAddress((void**)&xlo, g_xlo);
    cudaGetSymbolAddress((void**)&ehi, g_ehi);
    cudaGetSymbolAddress((void**)&elo, g_elo);

    cudaFuncSetAttribute(edge_kernel, cudaFuncAttributeMaxDynamicSharedMemorySize, E_SMEM);
    cudaFuncSetAttribute(node_kernel, cudaFuncAttributeMaxDynamicSharedMemorySize, N_SMEM);
    cudaFuncSetAttribute(node_pre_kernel, cudaFuncAttributeMaxDynamicSharedMemorySize, PRE_SMEM);

    // launch order arranged so edge_kernel is launch index 3 (ncu capture slot)
    split_kernel<<<512, 256>>>(x_in, xhi, xlo, (long)NN * 16);      // 0
    split_kernel<<<1024, 256>>>(e_in, ehi, elo, (long)NE * 16);     // 1

    const int EW0S = 192 * 64, EWS = 64 * 64, NW0S = 128 * 64;
    for (int i = 0; i < 3; i++) {
        const int fin = (i == 2) ? 1 : 0;
        node_pre_kernel<<<148, 256, PRE_SMEM>>>(ew0 + i * EW0S);    // 2, 5, 8
        edge_kernel<<<148, 256, E_SMEM>>>(                           // 3, 6, 9
            out_e, src, dst,
            ew0 + i * EW0S, eb0 + i * 64, ew1 + i * EWS, eb1 + i * 64,
            ew2 + i * EWS, eb2 + i * 64, eg + i * 64, ebt + i * 64, fin);
        node_kernel<<<148, 256, N_SMEM>>>(                           // 4, 7, 10
            out_x,
            nw0 + i * NW0S, nb0 + i * 64, nw1 + i * EWS, nb1 + i * 64,
            nw2 + i * EWS, nb2 + i * 64, ng + i * 64, nbt + i * 64, fin);
    }
}

// round 15
// speedup vs baseline: 1.3402x; 1.1037x over previous
#include <cuda_runtime.h>
#include <cuda_bf16.h>
#include <cstdint>

#define NN 50000
#define NE 800000
#define EPS_LN 1e-5f

// ---------------- scratch (no allocations allowed) ----------------
__device__ __align__(128) float g_agg[NN * 64];
__device__ __align__(128) float g_y[(size_t)NN * 128];   // fragment-major node partials
__device__ __align__(128) __nv_bfloat16 g_xhi[NN * 64], g_xlo[NN * 64];
__device__ __align__(128) __nv_bfloat16 g_ehi[(size_t)NE * 64], g_elo[(size_t)NE * 64];

// ---------------- helpers ----------------
__device__ __forceinline__ uint32_t smem_u32(const void* p) {
    uint32_t a;
    asm("{ .reg .u64 t; cvta.to.shared.u64 t, %1; cvt.u32.u64 %0, t; }" : "=r"(a) : "l"(p));
    return a;
}
__device__ __forceinline__ void split2(float f0, float f1, uint32_t& hi, uint32_t& lo) {
    uint32_t h;
    asm("cvt.rn.bf16x2.f32 %0, %1, %2;" : "=r"(h) : "f"(f1), "f"(f0));
    float h0 = __uint_as_float(h << 16);
    float h1 = __uint_as_float(h & 0xFFFF0000u);
    asm("cvt.rn.bf16x2.f32 %0, %1, %2;" : "=r"(lo) : "f"(f1 - h1), "f"(f0 - h0));
    hi = h;
}
__device__ __forceinline__ float2 join2(uint32_t hh, uint32_t ll) {
    float2 v;
    v.x = __uint_as_float(hh << 16) + __uint_as_float(ll << 16);
    v.y = __uint_as_float(hh & 0xFFFF0000u) + __uint_as_float(ll & 0xFFFF0000u);
    return v;
}
__device__ __forceinline__ void red2(float* p, float a, float b) {
    asm volatile("red.global.add.v2.f32 [%0], {%1, %2};" :: "l"(p), "f"(a), "f"(b) : "memory");
}
__device__ __forceinline__ void ldm4(uint32_t r[4], uint32_t a) {
    asm volatile("ldmatrix.sync.aligned.m8n8.x4.shared.b16 {%0,%1,%2,%3}, [%4];"
                 : "=r"(r[0]), "=r"(r[1]), "=r"(r[2]), "=r"(r[3]) : "r"(a));
}
__device__ __forceinline__ void mma16816(float d[4], const uint32_t a[4],
                                         uint32_t b0, uint32_t b1) {
    asm volatile("mma.sync.aligned.m16n8k16.row.col.f32.bf16.bf16.f32 "
                 "{%0,%1,%2,%3},{%4,%5,%6,%7},{%8,%9},{%0,%1,%2,%3};"
                 : "+f"(d[0]), "+f"(d[1]), "+f"(d[2]), "+f"(d[3])
                 : "r"(a[0]), "r"(a[1]), "r"(a[2]), "r"(a[3]), "r"(b0), "r"(b1));
}
__device__ __forceinline__ void cpasync16(uint32_t dst, const void* src) {
    asm volatile("cp.async.ca.shared.global [%0], [%1], 16;" :: "r"(dst), "l"(src));
}
#define CP_COMMIT() asm volatile("cp.async.commit_group;" ::: "memory")
#define CP_WAIT0()  asm volatile("cp.async.wait_group 0;" ::: "memory")
#define CP_WAIT1()  asm volatile("cp.async.wait_group 1;" ::: "memory")

// ---- A from smem, TWO m16 tiles share B; caller initializes d ----
template <int KT>
__device__ __forceinline__ void layer_smemA2(float (&d)[2][8][4],
        const uint32_t (&aHi)[2], const uint32_t (&aLo)[2],
        uint32_t bHi, uint32_t bLo, int bstep) {
#pragma unroll
    for (int kt = 0; kt < KT; kt++) {
        uint32_t ah[2][4], al[2][4];
        ldm4(ah[0], aHi[0] + kt * 32); ldm4(al[0], aLo[0] + kt * 32);
        ldm4(ah[1], aHi[1] + kt * 32); ldm4(al[1], aLo[1] + kt * 32);
        uint32_t bh[4][4], bl[4][4];
#pragma unroll
        for (int np = 0; np < 4; np++) {
            ldm4(bh[np], bHi + np * bstep + kt * 32);
            ldm4(bl[np], bLo + np * bstep + kt * 32);
        }
#pragma unroll
        for (int np = 0; np < 4; np++)
#pragma unroll
            for (int t = 0; t < 2; t++) {
                mma16816(d[t][2 * np],     ah[t], bh[np][0], bh[np][1]);
                mma16816(d[t][2 * np + 1], ah[t], bh[np][2], bh[np][3]);
            }
#pragma unroll
        for (int np = 0; np < 4; np++)
#pragma unroll
            for (int t = 0; t < 2; t++) {
                mma16816(d[t][2 * np],     ah[t], bl[np][0], bl[np][1]);
                mma16816(d[t][2 * np + 1], ah[t], bl[np][2], bl[np][3]);
            }
#pragma unroll
        for (int np = 0; np < 4; np++)
#pragma unroll
            for (int t = 0; t < 2; t++) {
                mma16816(d[t][2 * np],     al[t], bh[np][0], bh[np][1]);
                mma16816(d[t][2 * np + 1], al[t], bh[np][2], bh[np][3]);
            }
    }
}

// ---- A in registers (K=64), two tiles share B ----
__device__ __forceinline__ void layer_regA2(float (&d)[2][8][4],
        const uint32_t (&aH)[2][4][4], const uint32_t (&aL)[2][4][4],
        uint32_t bHi, uint32_t bLo, int bstep) {
#pragma unroll
    for (int t = 0; t < 2; t++)
#pragma unroll
        for (int nt = 0; nt < 8; nt++)
            d[t][nt][0] = d[t][nt][1] = d[t][nt][2] = d[t][nt][3] = 0.f;
#pragma unroll
    for (int kt = 0; kt < 4; kt++) {
        uint32_t bh[4][4], bl[4][4];
#pragma unroll
        for (int np = 0; np < 4; np++) {
            ldm4(bh[np], bHi + np * bstep + kt * 32);
            ldm4(bl[np], bLo + np * bstep + kt * 32);
        }
#pragma unroll
        for (int np = 0; np < 4; np++)
#pragma unroll
            for (int t = 0; t < 2; t++) {
                mma16816(d[t][2 * np],     aH[t][kt], bh[np][0], bh[np][1]);
                mma16816(d[t][2 * np + 1], aH[t][kt], bh[np][2], bh[np][3]);
            }
#pragma unroll
        for (int np = 0; np < 4; np++)
#pragma unroll
            for (int t = 0; t < 2; t++) {
                mma16816(d[t][2 * np],     aH[t][kt], bl[np][0], bl[np][1]);
                mma16816(d[t][2 * np + 1], aH[t][kt], bl[np][2], bl[np][3]);
            }
#pragma unroll
        for (int np = 0; np < 4; np++)
#pragma unroll
            for (int t = 0; t < 2; t++) {
                mma16816(d[t][2 * np],     aL[t][kt], bh[np][0], bh[np][1]);
                mma16816(d[t][2 * np + 1], aL[t][kt], bh[np][2], bh[np][3]);
            }
    }
}

// accumulator fragments -> next-layer A fragments, in registers
__device__ __forceinline__ void inter_reg2(const float (&d)[2][8][4], const float* bias, int c,
                                           uint32_t (&aH)[2][4][4], uint32_t (&aL)[2][4][4]) {
#pragma unroll
    for (int t = 0; t < 2; t++)
#pragma unroll
        for (int kt = 0; kt < 4; kt++) {
            float2 b0 = *(const float2*)(bias + 16 * kt + 2 * c);
            split2(fmaxf(d[t][2 * kt][0] + b0.x, 0.f), fmaxf(d[t][2 * kt][1] + b0.y, 0.f),
                   aH[t][kt][0], aL[t][kt][0]);
            split2(fmaxf(d[t][2 * kt][2] + b0.x, 0.f), fmaxf(d[t][2 * kt][3] + b0.y, 0.f),
                   aH[t][kt][1], aL[t][kt][1]);
            float2 b1 = *(const float2*)(bias + 16 * kt + 8 + 2 * c);
            split2(fmaxf(d[t][2 * kt + 1][0] + b1.x, 0.f), fmaxf(d[t][2 * kt + 1][1] + b1.y, 0.f),
                   aH[t][kt][2], aL[t][kt][2]);
            split2(fmaxf(d[t][2 * kt + 1][2] + b1.x, 0.f), fmaxf(d[t][2 * kt + 1][3] + b1.y, 0.f),
                   aH[t][kt][3], aL[t][kt][3]);
        }
}

// stage W[k][n] (row-major) as B[n][k] hi/lo with row stride bstr bytes
__device__ __forceinline__ void stage_w(char* dsth, char* dstl, const float* W,
                                        int K, int bstr, int tid, int nthr) {
    for (int idx = tid; idx < K * 64; idx += nthr) {
        int k = idx >> 6, n = idx & 63;
        float f = W[idx];
        __nv_bfloat16 h = __float2bfloat16_rn(f);
        __nv_bfloat16 l = __float2bfloat16_rn(f - __bfloat162float(h));
        int off = n * bstr + k * 2;
        *(__nv_bfloat16*)(dsth + off) = h;
        *(__nv_bfloat16*)(dstl + off) = l;
    }
}

// ================= NODE-PARTIAL PRECOMPUTE (MMA) + agg zero =================
// fragment-major y: y[n][half*64 + c*16 + nt*2 + b] = (x.W0half)[n][nt*8+2c+b]
#define PRE_SMEM 110592

__global__ void __launch_bounds__(256, 1) node_pre_kernel(const float* __restrict__ W0) {
    extern __shared__ char sm[];
    const int tid = threadIdx.x, wid = tid >> 5, lane = tid & 31;
    const uint32_t smb = smem_u32(sm);

    for (int i = blockIdx.x * blockDim.x + tid; i < NN * 16; i += gridDim.x * blockDim.x)
        ((float4*)g_agg)[i] = make_float4(0.f, 0.f, 0.f, 0.f);

    for (int idx = tid; idx < 128 * 64; idx += 256) {
        int j = idx >> 6, k = idx & 63;
        float f = W0[(k + ((j >= 64) ? 64 : 0)) * 64 + (j & 63)];
        __nv_bfloat16 h = __float2bfloat16_rn(f);
        __nv_bfloat16 l = __float2bfloat16_rn(f - __bfloat162float(h));
        int off = j * 144 + k * 2;
        *(__nv_bfloat16*)(sm + 73728 + off) = h;
        *(__nv_bfloat16*)(sm + 92160 + off) = l;
    }
    __syncthreads();

    char* aHiP = sm + wid * 4608;
    char* aLoP = sm + 36864 + wid * 4608;
    const uint32_t aHiB = smb + wid * 4608, aLoB = smb + 36864 + wid * 4608;

    const int tq = lane >> 3;
    const int rA = (lane & 7) + ((tq & 1) << 3);
    const int kA = (tq >> 1) << 3;
    const uint32_t aHi[2] = { aHiB + rA * 144 + kA * 2, aHiB + (16 + rA) * 144 + kA * 2 };
    const uint32_t aLo[2] = { aLoB + rA * 144 + kA * 2, aLoB + (16 + rA) * 144 + kA * 2 };
    const int ofsB144 = ((tq >> 1) * 8 + (lane & 7)) * 144 + (tq & 1) * 16;
    const uint32_t bh = smb + 73728 + ofsB144, bl = smb + 92160 + ofsB144;

    const int g = lane >> 2, c = lane & 3;
    const int grr = lane >> 3, gcc = lane & 7;

    const int NWT = (NN + 31) / 32;
    for (int wt = blockIdx.x * 8 + wid; wt < NWT; wt += gridDim.x * 8) {
        // coalesced gather: instr j covers 4 consecutive rows x 8 chunks
#pragma unroll
        for (int j = 0; j < 8; j++) {
            const int row = j * 4 + grr;
            const int n = wt * 32 + row;
            const int nc = (n < NN) ? n : (NN - 1);
            *(uint4*)(aHiP + row * 144 + gcc * 16) =
                *(const uint4*)((const char*)(g_xhi + (size_t)nc * 64) + gcc * 16);
            *(uint4*)(aLoP + row * 144 + gcc * 16) =
                *(const uint4*)((const char*)(g_xlo + (size_t)nc * 64) + gcc * 16);
        }
        __syncwarp();

#pragma unroll
        for (int half = 0; half < 2; half++) {
            float d[2][8][4];
#pragma unroll
            for (int t = 0; t < 2; t++)
#pragma unroll
                for (int nt = 0; nt < 8; nt++)
                    d[t][nt][0] = d[t][nt][1] = d[t][nt][2] = d[t][nt][3] = 0.f;
            layer_smemA2<4>(d, aHi, aLo, bh + half * 4 * 2304, bl + half * 4 * 2304, 2304);
#pragma unroll
            for (int t = 0; t < 2; t++) {
                const int n0 = wt * 32 + 16 * t + g, n1 = n0 + 8;
                const bool v0 = n0 < NN, v1 = n1 < NN;
                float2* o0 = (float2*)(g_y + (size_t)n0 * 128 + half * 64 + c * 16);
                float2* o1 = (float2*)(g_y + (size_t)n1 * 128 + half * 64 + c * 16);
#pragma unroll
                for (int nt = 0; nt < 8; nt++) {
                    if (v0) o0[nt] = make_float2(d[t][nt][0], d[t][nt][1]);
                    if (v1) o1[nt] = make_float2(d[t][nt][2], d[t][nt][3]);
                }
            }
        }
        __syncwarp();
    }
}

// ================= EDGE KERNEL =================
#define E_SMEM 204032

__global__ void __launch_bounds__(256, 1) edge_kernel(
    float* eout,
    const int* __restrict__ src, const int* __restrict__ dst,
    const float* __restrict__ W0, const float* __restrict__ b0,
    const float* __restrict__ W1, const float* __restrict__ b1,
    const float* __restrict__ W2, const float* __restrict__ b2,
    const float* __restrict__ gam, const float* __restrict__ bet, int fin)
{
    extern __shared__ char sm[];
    const int tid = threadIdx.x, wid = tid >> 5, lane = tid & 31;
    const uint32_t smb = smem_u32(sm);

    stage_w(sm + 147456, sm + 156672, W0 + 128 * 64, 64, 144, tid, 256);  // e-part of W0
    stage_w(sm + 165888, sm + 175104, W1, 64, 144, tid, 256);
    stage_w(sm + 184320, sm + 193536, W2, 64, 144, tid, 256);
    float* fb = (float*)(sm + 202752);
    if (tid < 64) {
        fb[tid] = b0[tid]; fb[64 + tid] = b1[tid]; fb[128 + tid] = b2[tid];
        fb[192 + tid] = gam[tid]; fb[256 + tid] = bet[tid];
    }
    __syncthreads();

    const uint32_t aHiB[2] = { smb + wid * 4608, smb + 36864 + wid * 4608 };
    const uint32_t aLoB[2] = { smb + 73728 + wid * 4608, smb + 110592 + wid * 4608 };

    const int tq = lane >> 3;
    const int rA = (lane & 7) + ((tq & 1) << 3);
    const int kA = (tq >> 1) << 3;
    const int ofsB144 = ((tq >> 1) * 8 + (lane & 7)) * 144 + (tq & 1) * 16;
    const uint32_t b1h = smb + 147456 + ofsB144, b1l = smb + 156672 + ofsB144;
    const uint32_t b2h = smb + 165888 + ofsB144, b2l = smb + 175104 + ofsB144;
    const uint32_t b3h = smb + 184320 + ofsB144, b3l = smb + 193536 + ofsB144;

    const int g = lane >> 2, c = lane & 3;
    const int grr = lane >> 3, gcc = lane & 7;

    const int NWT = NE / 32;
    const int stride = gridDim.x * 8;
    int wt = blockIdx.x * 8 + wid;
    int buf = 0;

    // prologue: coalesced async gather of tile 0
    if (wt < NWT) {
#pragma unroll
        for (int j = 0; j < 8; j++) {
            const int row = j * 4 + grr;
            const int ea = wt * 32 + row;
            cpasync16(aHiB[0] + row * 144 + gcc * 16,
                      (const char*)(g_ehi + (size_t)ea * 64) + gcc * 16);
            cpasync16(aLoB[0] + row * 144 + gcc * 16,
                      (const char*)(g_elo + (size_t)ea * 64) + gcc * 16);
        }
    }
    CP_COMMIT();

    for (; wt < NWT; wt += stride) {
        const int wtn = wt + stride;
        if (wtn < NWT) {
#pragma unroll
            for (int j = 0; j < 8; j++) {
                const int row = j * 4 + grr;
                const int ean = wtn * 32 + row;
                cpasync16(aHiB[buf ^ 1] + row * 144 + gcc * 16,
                          (const char*)(g_ehi + (size_t)ean * 64) + gcc * 16);
                cpasync16(aLoB[buf ^ 1] + row * 144 + gcc * 16,
                          (const char*)(g_elo + (size_t)ean * 64) + gcc * 16);
            }
            CP_COMMIT();
        }

        int sI[2][2], dI[2][2];
#pragma unroll
        for (int t = 0; t < 2; t++) {
            const int b = wt * 32 + 16 * t + g;
            sI[t][0] = __ldg(src + b); sI[t][1] = __ldg(src + b + 8);
            dI[t][0] = __ldg(dst + b); dI[t][1] = __ldg(dst + b + 8);
        }
        float d[2][8][4];
#pragma unroll
        for (int t = 0; t < 2; t++) {
            const float2* ys0 = (const float2*)(g_y + (size_t)sI[t][0] * 128 + c * 16);
            const float2* yd0 = (const float2*)(g_y + (size_t)dI[t][0] * 128 + 64 + c * 16);
            const float2* ys1 = (const float2*)(g_y + (size_t)sI[t][1] * 128 + c * 16);
            const float2* yd1 = (const float2*)(g_y + (size_t)dI[t][1] * 128 + 64 + c * 16);
#pragma unroll
            for (int nt = 0; nt < 8; nt++) {
                float2 a = ys0[nt], b = yd0[nt];
                d[t][nt][0] = a.x + b.x; d[t][nt][1] = a.y + b.y;
                a = ys1[nt]; b = yd1[nt];
                d[t][nt][2] = a.x + b.x; d[t][nt][3] = a.y + b.y;
            }
        }

        if (wtn < NWT) { CP_WAIT1(); } else { CP_WAIT0(); }
        __syncwarp();

        const uint32_t aHi[2] = { aHiB[buf] + rA * 144 + kA * 2,
                                  aHiB[buf] + (16 + rA) * 144 + kA * 2 };
        const uint32_t aLo[2] = { aLoB[buf] + rA * 144 + kA * 2,
                                  aLoB[buf] + (16 + rA) * 144 + kA * 2 };
        layer_smemA2<4>(d, aHi, aLo, b1h, b1l, 2304);

        uint32_t aH[2][4][4], aL[2][4][4];
        inter_reg2(d, fb, c, aH, aL);
        layer_regA2(d, aH, aL, b2h, b2l, 2304);
        inter_reg2(d, fb + 64, c, aH, aL);
        layer_regA2(d, aH, aL, b3h, b3l, 2304);

        char* aHiP = sm + (buf ? 36864 : 0) + wid * 4608;
        char* aLoP = sm + 73728 + (buf ? 36864 : 0) + wid * 4608;
        const float* b2v = fb + 128;
        const float* gmp = fb + 192;
        const float* btp = fb + 256;
#pragma unroll
        for (int t = 0; t < 2; t++) {
            const int r0 = 16 * t + g;
#pragma unroll
            for (int nt = 0; nt < 8; nt++) {
                int col = nt * 8 + 2 * c;
                float2 b = *(const float2*)(b2v + col);
                d[t][nt][0] += b.x; d[t][nt][1] += b.y;
                d[t][nt][2] += b.x; d[t][nt][3] += b.y;
            }
            float s0 = 0, q0 = 0, s1 = 0, q1 = 0;
#pragma unroll
            for (int nt = 0; nt < 8; nt++) {
                s0 += d[t][nt][0] + d[t][nt][1];
                q0 += d[t][nt][0] * d[t][nt][0] + d[t][nt][1] * d[t][nt][1];
                s1 += d[t][nt][2] + d[t][nt][3];
                q1 += d[t][nt][2] * d[t][nt][2] + d[t][nt][3] * d[t][nt][3];
            }
#pragma unroll
            for (int o = 1; o <= 2; o <<= 1) {
                s0 += __shfl_xor_sync(0xffffffffu, s0, o);
                q0 += __shfl_xor_sync(0xffffffffu, q0, o);
                s1 += __shfl_xor_sync(0xffffffffu, s1, o);
                q1 += __shfl_xor_sync(0xffffffffu, q1, o);
            }
            const float mu0 = s0 * (1.f / 64.f), mu1 = s1 * (1.f / 64.f);
            const float ri0 = rsqrtf(q0 * (1.f / 64.f) - mu0 * mu0 + EPS_LN);
            const float ri1 = rsqrtf(q1 * (1.f / 64.f) - mu1 * mu1 + EPS_LN);
            const int ea0 = wt * 32 + r0, ea1 = ea0 + 8;
            float* eo0 = eout + (size_t)ea0 * 64;
            float* eo1 = eout + (size_t)ea1 * 64;
            float* ag0 = g_agg + (size_t)dI[t][0] * 64;
            float* ag1 = g_agg + (size_t)dI[t][1] * 64;
#pragma unroll
            for (int nt = 0; nt < 8; nt++) {
                int col = nt * 8 + 2 * c;
                float2 gmv = *(const float2*)(gmp + col);
                float2 btv = *(const float2*)(btp + col);
                float2 e0 = join2(*(const uint32_t*)(aHiP + r0 * 144 + col * 2),
                                  *(const uint32_t*)(aLoP + r0 * 144 + col * 2));
                float2 e1 = join2(*(const uint32_t*)(aHiP + (r0 + 8) * 144 + col * 2),
                                  *(const uint32_t*)(aLoP + (r0 + 8) * 144 + col * 2));
                float o0 = (d[t][nt][0] - mu0) * ri0 * gmv.x + btv.x + e0.x;
                float o1 = (d[t][nt][1] - mu0) * ri0 * gmv.y + btv.y + e0.y;
                float p0 = (d[t][nt][2] - mu1) * ri1 * gmv.x + btv.x + e1.x;
                float p1 = (d[t][nt][3] - mu1) * ri1 * gmv.y + btv.y + e1.y;
                red2(ag0 + col, o0, o1);
                red2(ag1 + col, p0, p1);
                if (fin) {
                    *(float2*)(eo0 + col) = make_float2(o0, o1);
                    *(float2*)(eo1 + col) = make_float2(p0, p1);
                } else {
                    uint32_t hh, ll;
                    split2(o0, o1, hh, ll);
                    *(uint32_t*)((char*)g_ehi + ((size_t)ea0 * 64 + col) * 2) = hh;
                    *(uint32_t*)((char*)g_elo + ((size_t)ea0 * 64 + col) * 2) = ll;
                    split2(p0, p1, hh, ll);
                    *(uint32_t*)((char*)g_ehi + ((size_t)ea1 * 64 + col) * 2) = hh;
                    *(uint32_t*)((char*)g_elo + ((size_t)ea1 * 64 + col) * 2) = ll;
                }
            }
        }
        buf ^= 1;
    }
}

// ================= NODE KERNEL =================
#define N_SMEM 212224

__global__ void __launch_bounds__(256, 1) node_kernel(
    float* xout,
    const float* __restrict__ W0, const float* __restrict__ b0,
    const float* __restrict__ W1, const float* __restrict__ b1,
    const float* __restrict__ W2, const float* __restrict__ b2,
    const float* __restrict__ gam, const float* __restrict__ bet, int fin)
{
    extern __shared__ char sm[];
    const int tid = threadIdx.x, wid = tid >> 5, lane = tid & 31;
    const uint32_t smb = smem_u32(sm);

    stage_w(sm + 139264, sm + 156672, W0, 128, 272, tid, 256);
    stage_w(sm + 174080, sm + 183296, W1, 64, 144, tid, 256);
    stage_w(sm + 192512, sm + 201728, W2, 64, 144, tid, 256);
    float* fb = (float*)(sm + 210944);
    if (tid < 64) {
        fb[tid] = b0[tid]; fb[64 + tid] = b1[tid]; fb[128 + tid] = b2[tid];
        fb[192 + tid] = gam[tid]; fb[256 + tid] = bet[tid];
    }
    __syncthreads();

    char* aHiP = sm + wid * 8704;
    char* aLoP = sm + 69632 + wid * 8704;
    const uint32_t aHiB = smb + wid * 8704, aLoB = smb + 69632 + wid * 8704;

    const int tq = lane >> 3;
    const int rA = (lane & 7) + ((tq & 1) << 3);
    const int kA = (tq >> 1) << 3;
    const uint32_t aHi[2] = { aHiB + rA * 272 + kA * 2, aHiB + (16 + rA) * 272 + kA * 2 };
    const uint32_t aLo[2] = { aLoB + rA * 272 + kA * 2, aLoB + (16 + rA) * 272 + kA * 2 };
    const int ofsB272 = ((tq >> 1) * 8 + (lane & 7)) * 272 + (tq & 1) * 16;
    const int ofsB144 = ((tq >> 1) * 8 + (lane & 7)) * 144 + (tq & 1) * 16;
    const uint32_t b1h = smb + 139264 + ofsB272, b1l = smb + 156672 + ofsB272;
    const uint32_t b2h = smb + 174080 + ofsB144, b2l = smb + 183296 + ofsB144;
    const uint32_t b3h = smb + 192512 + ofsB144, b3l = smb + 201728 + ofsB144;

    const int g = lane >> 2, c = lane & 3;
    const int grr = lane >> 3, gcc = lane & 7;
    const int arr = lane >> 4, acc_ = lane & 15;

    const int NWT = (NN + 31) / 32;
    for (int wt = blockIdx.x * 8 + wid; wt < NWT; wt += gridDim.x * 8) {
        // coalesced gather: x rows (128B) then agg rows (256B fp32, split inline)
#pragma unroll
        for (int j = 0; j < 8; j++) {
            const int row = j * 4 + grr;
            const int n = wt * 32 + row;
            const int nc = (n < NN) ? n : (NN - 1);
            *(uint4*)(aHiP + row * 272 + gcc * 16) =
                *(const uint4*)((const char*)(g_xhi + (size_t)nc * 64) + gcc * 16);
            *(uint4*)(aLoP + row * 272 + gcc * 16) =
                *(const uint4*)((const char*)(g_xlo + (size_t)nc * 64) + gcc * 16);
        }
#pragma unroll
        for (int j = 0; j < 16; j++) {
            const int row = j * 2 + arr;
            const int n = wt * 32 + row;
            const int nc = (n < NN) ? n : (NN - 1);
            float4 v = *(const float4*)(g_agg + (size_t)nc * 64 + acc_ * 4);
            uint32_t h0, l0, h1, l1;
            split2(v.x, v.y, h0, l0);
            split2(v.z, v.w, h1, l1);
            *(uint2*)(aHiP + row * 272 + 128 + acc_ * 8) = make_uint2(h0, h1);
            *(uint2*)(aLoP + row * 272 + 128 + acc_ * 8) = make_uint2(l0, l1);
        }
        __syncwarp();

        float d[2][8][4];
#pragma unroll
        for (int t = 0; t < 2; t++)
#pragma unroll
            for (int nt = 0; nt < 8; nt++)
                d[t][nt][0] = d[t][nt][1] = d[t][nt][2] = d[t][nt][3] = 0.f;
        layer_smemA2<8>(d, aHi, aLo, b1h, b1l, 4352);
        uint32_t aH[2][4][4], aL[2][4][4];
        inter_reg2(d, fb, c, aH, aL);
        layer_regA2(d, aH, aL, b2h, b2l, 2304);
        inter_reg2(d, fb + 64, c, aH, aL);
        layer_regA2(d, aH, aL, b3h, b3l, 2304);

        const float* b2v = fb + 128;
        const float* gmp = fb + 192;
        const float* btp = fb + 256;
#pragma unroll
        for (int t = 0; t < 2; t++) {
            const int r0 = 16 * t + g;
#pragma unroll
            for (int nt = 0; nt < 8; nt++) {
                int col = nt * 8 + 2 * c;
                float2 b = *(const float2*)(b2v + col);
                d[t][nt][0] += b.x; d[t][nt][1] += b.y;
                d[t][nt][2] += b.x; d[t][nt][3] += b.y;
            }
            float s0 = 0, q0 = 0, s1 = 0, q1 = 0;
#pragma unroll
            for (int nt = 0; nt < 8; nt++) {
                s0 += d[t][nt][0] + d[t][nt][1];
                q0 += d[t][nt][0] * d[t][nt][0] + d[t][nt][1] * d[t][nt][1];
                s1 += d[t][nt][2] + d[t][nt][3];
                q1 += d[t][nt][2] * d[t][nt][2] + d[t][nt][3] * d[t][nt][3];
            }
#pragma unroll
            for (int o = 1; o <= 2; o <<= 1) {
                s0 += __shfl_xor_sync(0xffffffffu, s0, o);
                q0 += __shfl_xor_sync(0xffffffffu, q0, o);
                s1 += __shfl_xor_sync(0xffffffffu, s1, o);
                q1 += __shfl_xor_sync(0xffffffffu, q1, o);
            }
            const float mu0 = s0 * (1.f / 64.f), mu1 = s1 * (1.f / 64.f);
            const float ri0 = rsqrtf(q0 * (1.f / 64.f) - mu0 * mu0 + EPS_LN);
            const float ri1 = rsqrtf(q1 * (1.f / 64.f) - mu1 * mu1 + EPS_LN);
            const int n0 = wt * 32 + r0, n1 = n0 + 8;
            const bool v0 = n0 < NN, v1 = n1 < NN;
            float* xo0 = xout + (size_t)n0 * 64;
            float* xo1 = xout + (size_t)n1 * 64;
#pragma unroll
            for (int nt = 0; nt < 8; nt++) {
                int col = nt * 8 + 2 * c;
                float2 gmv = *(const float2*)(gmp + col);
                float2 btv = *(const float2*)(btp + col);
                float2 x0 = join2(*(const uint32_t*)(aHiP + r0 * 272 + col * 2),
                                  *(const uint32_t*)(aLoP + r0 * 272 + col * 2));
                float2 x1 = join2(*(const uint32_t*)(aHiP + (r0 + 8) * 272 + col * 2),
                                  *(const uint32_t*)(aLoP + (r0 + 8) * 272 + col * 2));
                float o0 = (d[t][nt][0] - mu0) * ri0 * gmv.x + btv.x + x0.x;
                float o1 = (d[t][nt][1] - mu0) * ri0 * gmv.y + btv.y + x0.y;
                float p0 = (d[t][nt][2] - mu1) * ri1 * gmv.x + btv.x + x1.x;
                float p1 = (d[t][nt][3] - mu1) * ri1 * gmv.y + btv.y + x1.y;
                if (fin) {
                    if (v0) *(float2*)(xo0 + col) = make_float2(o0, o1);
                    if (v1) *(float2*)(xo1 + col) = make_float2(p0, p1);
                } else {
                    uint32_t hh, ll;
                    if (v0) {
                        split2(o0, o1, hh, ll);
                        *(uint32_t*)((char*)g_xhi + ((size_t)n0 * 64 + col) * 2) = hh;
                        *(uint32_t*)((char*)g_xlo + ((size_t)n0 * 64 + col) * 2) = ll;
                    }
                    if (v1) {
                        split2(p0, p1, hh, ll);
                        *(uint32_t*)((char*)g_xhi + ((size_t)n1 * 64 + col) * 2) = hh;
                        *(uint32_t*)((char*)g_xlo + ((size_t)n1 * 64 + col) * 2) = ll;
                    }
                }
            }
        }
        __syncwarp();
    }
}

// ================= streaming split =================
__global__ void split_kernel(const float* __restrict__ in, __nv_bfloat16* __restrict__ hi,
                             __nv_bfloat16* __restrict__ lo, long n4) {
    for (long i = blockIdx.x * (long)blockDim.x + threadIdx.x; i < n4;
         i += (long)gridDim.x * blockDim.x) {
        float4 v = ((const float4*)in)[i];
        uint32_t h0, l0, h1, l1;
        split2(v.x, v.y, h0, l0);
        split2(v.z, v.w, h1, l1);
        ((uint2*)hi)[i] = make_uint2(h0, h1);
        ((uint2*)lo)[i] = make_uint2(l0, l1);
    }
}

// ================= launcher =================
extern "C" void kernel_launch(void* const* d_in, const int* in_sizes, int n_in,
                              void* d_out, int out_size) {
    const float* x_in = (const float*)d_in[0];
    const float* e_in = (const float*)d_in[1];
    const int* ei = (const int*)d_in[2];
    const int *src = ei, *dst = ei + NE;
    const float* ew0 = (const float*)d_in[3];  const float* eb0 = (const float*)d_in[4];
    const float* ew1 = (const float*)d_in[5];  const float* eb1 = (const float*)d_in[6];
    const float* ew2 = (const float*)d_in[7];  const float* eb2 = (const float*)d_in[8];
    const float* eg  = (const float*)d_in[9];  const float* ebt = (const float*)d_in[10];
    const float* nw0 = (const float*)d_in[11]; const float* nb0 = (const float*)d_in[12];
    const float* nw1 = (const float*)d_in[13]; const float* nb1 = (const float*)d_in[14];
    const float* nw2 = (const float*)d_in[15]; const float* nb2 = (const float*)d_in[16];
    const float* ng  = (const float*)d_in[17]; const float* nbt = (const float*)d_in[18];

    float* out_x = (float*)d_out;
    float* out_e = (float*)d_out + (size_t)NN * 64;

    __nv_bfloat16 *xhi, *xlo, *ehi, *elo;
    cudaGetSymbolAddress((void**)&xhi, g_xhi);
    cudaGetSymbolAddress((void**)&xlo, g_xlo);
    cudaGetSymbolAddress((void**)&ehi, g_ehi);
    cudaGetSymbolAddress((void**)&elo, g_elo);

    cudaFuncSetAttribute(edge_kernel, cudaFuncAttributeMaxDynamicSharedMemorySize, E_SMEM);
    cudaFuncSetAttribute(node_kernel, cudaFuncAttributeMaxDynamicSharedMemorySize, N_SMEM);
    cudaFuncSetAttribute(node_pre_kernel, cudaFuncAttributeMaxDynamicSharedMemorySize, PRE_SMEM);

    // keep edge_kernel at launch index 3 (ncu capture slot)
    split_kernel<<<512, 256>>>(x_in, xhi, xlo, (long)NN * 16);      // 0
    split_kernel<<<1024, 256>>>(e_in, ehi, elo, (long)NE * 16);     // 1

    const int EW0S = 192 * 64, EWS = 64 * 64, NW0S = 128 * 64;
    for (int i = 0; i < 3; i++) {
        const int fin = (i == 2) ? 1 : 0;
        node_pre_kernel<<<148, 256, PRE_SMEM>>>(ew0 + i * EW0S);    // 2, 5, 8
        edge_kernel<<<148, 256, E_SMEM>>>(                           // 3, 6, 9
            out_e, src, dst,
            ew0 + i * EW0S, eb0 + i * 64, ew1 + i * EWS, eb1 + i * 64,
            ew2 + i * EWS, eb2 + i * 64, eg + i * 64, ebt + i * 64, fin);
        node_kernel<<<148, 256, N_SMEM>>>(                           // 4, 7, 10
            out_x,
            nw0 + i * NW0S, nb0 + i * 64, nw1 + i * EWS, nb1 + i * 64,
            nw2 + i * EWS, nb2 + i * 64, ng + i * 64, nbt + i * 64, fin);
    }
}